// round 9
// baseline (speedup 1.0000x reference)
#include <cuda_runtime.h>
#include <math.h>
#include <stdint.h>

#define NN 8192
#define KK 512
#define FF 64
#define SPLITJ 8
#define JCHUNK (NN / SPLITJ)   // 1024
#define BI 64
#define BJ 64
#define NT (JCHUNK / BJ)       // 16

// smem layout (bytes)
#define ADSTG 17408                 // 64 rows * 272B
#define SM_AD 0                     // 2 stages
#define SM_AJ (SM_AD + 2 * ADSTG)
#define SM_PM (SM_AJ + 2 * ADSTG)   // P bf16 (mma j-half): hi 5120 + lo 5120
#define SM_PF (SM_PM + 10240)       // P fp32 (ffma j-half): 64*144
#define SM_HT (SM_PF + 9216)        // Ht bf16: hi 5120 + lo 5120
#define SM_HS (SM_HT + 10240)       // H fp32 [32j][64f] = 8192
#define SM_HR (SM_HS + 8192)        // 4096
#define SM_BYTES (SM_HR + 4096)     // 111616

__device__ float g_h[(size_t)NN * FF];
__device__ float g_hl[NN];
__device__ float g_hr[NN];
__device__ float g_scalars[4];
__device__ uint4 g_hT2[128 * 512];                  // per-64-tile: lower 32j transposed bf16 hi|lo, 1 MB
__device__ float g_acc[(size_t)SPLITJ * NN * FF];   // ffma partials, 16 MB
__device__ float g_acc2[(size_t)SPLITJ * NN * FF];  // mma partials, 16 MB
__device__ float g_Z[SPLITJ * NN];

// ---------- helpers ----------
__device__ __forceinline__ unsigned long long pk2(float x, float y) {
    unsigned long long r; asm("mov.b64 %0, {%1,%2};" : "=l"(r) : "f"(x), "f"(y)); return r;
}
__device__ __forceinline__ void fma2(unsigned long long& d, unsigned long long a, unsigned long long b) {
    asm("fma.rn.f32x2 %0, %1, %2, %0;" : "+l"(d) : "l"(a), "l"(b));
}
__device__ __forceinline__ float2 upk(unsigned long long v) {
    float2 f; asm("mov.b64 {%0,%1}, %2;" : "=f"(f.x), "=f"(f.y) : "l"(v)); return f;
}
__device__ __forceinline__ uint32_t smem_u32(const void* p) {
    uint32_t a; asm("{ .reg .u64 t; cvta.to.shared.u64 t, %1; cvt.u32.u64 %0, t; }" : "=r"(a) : "l"(p)); return a;
}
__device__ __forceinline__ void lds_u64x2(unsigned long long& a, unsigned long long& b, const float* p) {
    asm volatile("ld.shared.v2.u64 {%0,%1}, [%2];" : "=l"(a), "=l"(b)
                 : "r"((unsigned)__cvta_generic_to_shared(p)));
}
__device__ __forceinline__ void cpa16(uint32_t dst, const void* src) {
    asm volatile("cp.async.cg.shared.global [%0], [%1], 16;" :: "r"(dst), "l"(src));
}
#define CP_COMMIT()  asm volatile("cp.async.commit_group;" ::: "memory")
#define CP_WAIT1()   asm volatile("cp.async.wait_group 1;" ::: "memory")
#define CP_WAITALL() asm volatile("cp.async.wait_all;" ::: "memory")

__device__ __forceinline__ uint32_t bf16x2_of(float lo, float hi) {
    uint32_t r; asm("cvt.rn.bf16x2.f32 %0, %1, %2;" : "=r"(r) : "f"(hi), "f"(lo)); return r;
}
__device__ __forceinline__ void ldm4(uint32_t* r, uint32_t addr) {
    asm volatile("ldmatrix.sync.aligned.m8n8.x4.shared.b16 {%0,%1,%2,%3}, [%4];"
                 : "=r"(r[0]), "=r"(r[1]), "=r"(r[2]), "=r"(r[3]) : "r"(addr));
}
// mma.sync on f32 accumulators stored as packed u64 pairs (ptxas elides the movs)
__device__ __forceinline__ void mma16816p(unsigned long long& d01, unsigned long long& d23,
                                          const uint32_t* a, uint32_t b0, uint32_t b1) {
    asm volatile("{\n\t"
        ".reg .f32 p0,p1,p2,p3;\n\t"
        "mov.b64 {p0,p1}, %0;\n\t"
        "mov.b64 {p2,p3}, %1;\n\t"
        "mma.sync.aligned.m16n8k16.row.col.f32.bf16.bf16.f32 "
        "{p0,p1,p2,p3}, {%2,%3,%4,%5}, {%6,%7}, {p0,p1,p2,p3};\n\t"
        "mov.b64 %0, {p0,p1};\n\t"
        "mov.b64 %1, {p2,p3};\n\t}"
        : "+l"(d01), "+l"(d23)
        : "r"(a[0]), "r"(a[1]), "r"(a[2]), "r"(a[3]), "r"(b0), "r"(b1));
}

// ============ A: h = input @ W ============
__global__ void __launch_bounds__(256) k_gemm_h(const float* __restrict__ X, const float* __restrict__ W) {
    __shared__ float xs[32][68];
    const int t = threadIdx.x, tx = t & 15, ty = t >> 4, i0 = blockIdx.x * 64;
    unsigned long long acc[4][2];
#pragma unroll
    for (int r = 0; r < 4; r++) { acc[r][0] = 0ULL; acc[r][1] = 0ULL; }
    for (int c0 = 0; c0 < KK; c0 += 32) {
#pragma unroll
        for (int q = 0; q < 8; q++) {
            int lin = t + 256 * q, row = lin >> 5, kk = lin & 31;
            xs[kk][row] = X[(size_t)(i0 + row) * KK + c0 + kk];
        }
        __syncthreads();
#pragma unroll
        for (int kk = 0; kk < 32; kk++) {
            float4 w4 = *(const float4*)&W[(size_t)(c0 + kk) * FF + 4 * tx];
            unsigned long long w01 = pk2(w4.x, w4.y), w23 = pk2(w4.z, w4.w);
            float4 a4 = *(const float4*)&xs[kk][4 * ty];
            float av[4] = {a4.x, a4.y, a4.z, a4.w};
#pragma unroll
            for (int r = 0; r < 4; r++) {
                unsigned long long ar = pk2(av[r], av[r]);
                fma2(acc[r][0], ar, w01); fma2(acc[r][1], ar, w23);
            }
        }
        __syncthreads();
    }
#pragma unroll
    for (int r = 0; r < 4; r++) {
        float2 lo = upk(acc[r][0]), hi = upk(acc[r][1]);
        *(float4*)&g_h[(size_t)(i0 + 4 * ty + r) * FF + 4 * tx] = make_float4(lo.x, lo.y, hi.x, hi.y);
    }
}

// ============ B: hl/hr ============
__global__ void __launch_bounds__(256) k_hlr(const float* __restrict__ a) {
    __shared__ float a1s[FF], a2s[FF];
    const int t = threadIdx.x;
    if (t < FF) a1s[t] = a[t]; else if (t < 2 * FF) a2s[t - FF] = a[t];
    __syncthreads();
    const int row = blockIdx.x * 256 + t;
    float s1 = 0.f, s2 = 0.f;
#pragma unroll
    for (int q = 0; q < 16; q++) {
        float4 h4 = *(const float4*)&g_h[(size_t)row * FF + 4 * q];
        s1 = fmaf(h4.x, a1s[4*q], fmaf(h4.y, a1s[4*q+1], fmaf(h4.z, a1s[4*q+2], fmaf(h4.w, a1s[4*q+3], s1))));
        s2 = fmaf(h4.x, a2s[4*q], fmaf(h4.y, a2s[4*q+1], fmaf(h4.z, a2s[4*q+2], fmaf(h4.w, a2s[4*q+3], s2))));
    }
    g_hl[row] = s1; g_hr[row] = s2;
}

// ============ C: scalars ============
__global__ void k_scalars(const float* __restrict__ Wsi, const float* __restrict__ Wei) {
    __shared__ float red[256];
    const int t = threadIdx.x;
    float m = -3.4e38f;
    for (int i = t; i < NN; i += 256) m = fmaxf(m, g_hr[i]);
    red[t] = m; __syncthreads();
    for (int s = 128; s > 0; s >>= 1) { if (t < s) red[t] = fmaxf(red[t], red[t + s]); __syncthreads(); }
    if (t == 0) { g_scalars[0] = red[0]; g_scalars[1] = fabsf(Wei[0]); g_scalars[2] = fabsf(Wsi[0]); }
}

// ============ Prep: lower-32j of each 64-tile -> [var][f][jpair] bf16 ============
__global__ void __launch_bounds__(256) k_prep_ht() {
    __shared__ float hs[32 * 68];
    const int t = threadIdx.x, T = blockIdx.x, j0 = T * 64;
#pragma unroll
    for (int k = 0; k < 2; k++) {
        int id = t + 256 * k;               // float4 id 0..511
        int j = id >> 4, f4 = id & 15;
        *(float4*)&hs[j * 68 + f4 * 4] = *(const float4*)&g_h[(size_t)(j0 + j) * FF + f4 * 4];
    }
    __syncthreads();
    const int f = t >> 2, q = t & 3;
    uint32_t hiv[4], lov[4];
#pragma unroll
    for (int s = 0; s < 4; s++) {
        int j = 2 * (q * 4 + s);
        float v0 = hs[j * 68 + f], v1 = hs[(j + 1) * 68 + f];
        uint32_t h2 = bf16x2_of(v0, v1);
        hiv[s] = h2;
        lov[s] = bf16x2_of(v0 - __uint_as_float(h2 << 16), v1 - __uint_as_float(h2 & 0xffff0000u));
    }
    g_hT2[T * 512 + f * 4 + q]       = make_uint4(hiv[0], hiv[1], hiv[2], hiv[3]);
    g_hT2[T * 512 + 256 + f * 4 + q] = make_uint4(lov[0], lov[1], lov[2], lov[3]);
}

// ============ D: fused attention — dual-pipe (HMMA + FFMA2) ============
__device__ __forceinline__ void issue_adaj(const float* __restrict__ adj_ad, const int* __restrict__ adj,
                                           int i0, int j0, int t, uint32_t ad_dst, uint32_t aj_dst) {
#pragma unroll
    for (int k = 0; k < 4; k++) {
        int c = k * 256 + t, r = c >> 4, ch = c & 15;
        cpa16(ad_dst + r * 272 + ch * 16, adj_ad + (size_t)(i0 + r) * NN + j0 + ch * 4);
        cpa16(aj_dst + r * 272 + ch * 16, adj    + (size_t)(i0 + r) * NN + j0 + ch * 4);
    }
}

__global__ void __launch_bounds__(256, 2) k_attn(const float* __restrict__ adj_ad,
                                                 const int* __restrict__ adj) {
    extern __shared__ float4 smem4[];
    char* base = (char*)smem4;
    const uint32_t sb = smem_u32(base);

    const int t = threadIdx.x, wid = t >> 5, l = t & 31;
    const int i0 = blockIdx.x * BI, split = blockIdx.y, j0b = split * JCHUNK;

    *(float4*)(base + SM_HR + 16 * t) = *(const float4*)&g_hr[j0b + 4 * t];

    const float hrmax = g_scalars[0], wei = g_scalars[1], wsi = g_scalars[2];
    const int r1 = t >> 2, q1 = t & 3;
    const float hl_r = g_hl[i0 + r1];
    float smax = hl_r + hrmax;
    const float m_r = fmaf(wei, fmaxf(smax, 0.2f * smax), wsi);

    issue_adaj(adj_ad, adj, i0, j0b, t, sb + SM_AD, sb + SM_AJ);
    CP_COMMIT();

    // register prefetch for tile 0 (Ht bf16 8KB + H fp32 8KB)
    uint4 hreg[4];
    {
        const int Tt = split * 16;
        hreg[0] = g_hT2[Tt * 512 + t];
        hreg[1] = g_hT2[Tt * 512 + 256 + t];
        const uint4* hsrc = (const uint4*)&g_h[(size_t)(j0b + 32) * FF];
        hreg[2] = hsrc[t]; hreg[3] = hsrc[t + 256];
    }

    unsigned long long accu[16];
#pragma unroll
    for (int i = 0; i < 16; i++) accu[i] = 0ULL;
    float zl = 0.f;

    for (int jt = 0; jt < NT; jt++) {
        const int cst = jt & 1, nst = (jt + 1) & 1;
        const int jn = (jt + 1 < NT) ? jt + 1 : NT - 1;
        issue_adaj(adj_ad, adj, i0, j0b + jn * BJ, t, sb + SM_AD + nst * ADSTG, sb + SM_AJ + nst * ADSTG);
        CP_COMMIT();
        CP_WAIT1();
        __syncthreads();   // adaj[jt] visible; all phase2(jt-1) done with P/Ht/Hs

        // ---- stage Ht (bf16) and Hs (fp32) from regs ----
#pragma unroll
        for (int k = 0; k < 2; k++) {
            int id = t + 256 * k, var = id >> 8, rem = id & 255, f = rem >> 2, jq = rem & 3;
            *(uint4*)(base + SM_HT + var * 5120 + f * 80 + jq * 16) = hreg[k];
        }
        ((uint4*)(base + SM_HS))[t]       = hreg[2];
        ((uint4*)(base + SM_HS))[t + 256] = hreg[3];

        // ---- phase 1: 16 p per thread; q1<2 -> bf16 split, q1>=2 -> fp32 ----
        {
            const float* ads = (const float*)(base + SM_AD + cst * ADSTG) + r1 * 68 + q1 * 16;
            const int*   ajs = (const int*)  (base + SM_AJ + cst * ADSTG) + r1 * 68 + q1 * 16;
            const float* hrs = (const float*)(base + SM_HR) + jt * 64 + q1 * 16;
            float pv[16];
#pragma unroll
            for (int k = 0; k < 4; k++) {
                float4 ad4 = *(const float4*)(ads + 4 * k);
                int4   aj4 = *(const int4*)(ajs + 4 * k);
                float4 hr4 = *(const float4*)(hrs + 4 * k);
                float s0 = hl_r + hr4.x, l0 = fmaxf(s0, 0.2f * s0);
                float s1 = hl_r + hr4.y, l1 = fmaxf(s1, 0.2f * s1);
                float s2 = hl_r + hr4.z, l2 = fmaxf(s2, 0.2f * s2);
                float s3 = hl_r + hr4.w, l3 = fmaxf(s3, 0.2f * s3);
                pv[4*k+0] = (aj4.x > 0) ? __expf(fmaf(wei, l0, fmaf(wsi, ad4.x, -m_r))) : 0.f;
                pv[4*k+1] = (aj4.y > 0) ? __expf(fmaf(wei, l1, fmaf(wsi, ad4.y, -m_r))) : 0.f;
                pv[4*k+2] = (aj4.z > 0) ? __expf(fmaf(wei, l2, fmaf(wsi, ad4.z, -m_r))) : 0.f;
                pv[4*k+3] = (aj4.w > 0) ? __expf(fmaf(wei, l3, fmaf(wsi, ad4.w, -m_r))) : 0.f;
                zl += (pv[4*k] + pv[4*k+1]) + (pv[4*k+2] + pv[4*k+3]);
            }
            if (q1 < 2) {
                uint32_t hiv[8], lov[8];
#pragma unroll
                for (int k = 0; k < 8; k++) {
                    uint32_t h2 = bf16x2_of(pv[2*k], pv[2*k+1]);
                    hiv[k] = h2;
                    lov[k] = bf16x2_of(pv[2*k]   - __uint_as_float(h2 << 16),
                                       pv[2*k+1] - __uint_as_float(h2 & 0xffff0000u));
                }
                char* pm = base + SM_PM + r1 * 80 + q1 * 32;
                *(uint4*)pm          = make_uint4(hiv[0], hiv[1], hiv[2], hiv[3]);
                *(uint4*)(pm + 16)   = make_uint4(hiv[4], hiv[5], hiv[6], hiv[7]);
                *(uint4*)(pm + 5120) = make_uint4(lov[0], lov[1], lov[2], lov[3]);
                *(uint4*)(pm + 5136) = make_uint4(lov[4], lov[5], lov[6], lov[7]);
            } else {
                char* pf = base + SM_PF + r1 * 144 + (q1 - 2) * 64;
#pragma unroll
                for (int k = 0; k < 4; k++)
                    *(float4*)(pf + 16 * k) = make_float4(pv[4*k], pv[4*k+1], pv[4*k+2], pv[4*k+3]);
            }
        }

        // prefetch next tile's H into regs (L2-hot)
        if (jt + 1 < NT) {
            const int Tt = split * 16 + jt + 1;
            hreg[0] = g_hT2[Tt * 512 + t];
            hreg[1] = g_hT2[Tt * 512 + 256 + t];
            const uint4* hsrc = (const uint4*)&g_h[(size_t)(j0b + (jt + 1) * BJ + 32) * FF];
            hreg[2] = hsrc[t]; hreg[3] = hsrc[t + 256];
        }
        __syncthreads();   // P/Ht/Hs ready

        // ---- phase 2: warp-specialized dual pipe ----
        if (wid >= 4) {
            // tensor path: j 0..31, 3-term bf16 split
            const int iw = wid - 4;
            const uint32_t aRow = (uint32_t)((l & 7) | (l & 8));
            const uint32_t aOff = (uint32_t)(16 * iw + aRow) * 80u + (uint32_t)(((l >> 4) & 1) * 16);
            const uint32_t aHi = sb + SM_PM + aOff, aLo = aHi + 5120u;
            const uint32_t bRowL = (uint32_t)((l & 7) | (((l >> 4) & 1) << 3));
            const uint32_t bOffL = bRowL * 80u + (uint32_t)(((l >> 3) & 1) * 16);
#pragma unroll
            for (int ks = 0; ks < 2; ks++) {
                const uint32_t ka = (uint32_t)ks * 32u;
                uint32_t aH[4], aL[4];
                ldm4(aH, aHi + ka);
                ldm4(aL, aLo + ka);
#pragma unroll
                for (int nb2 = 0; nb2 < 4; nb2++) {
                    uint32_t bH[4], bL[4];
                    const uint32_t bb = sb + SM_HT + (uint32_t)nb2 * 1280u + bOffL + ka;
                    ldm4(bH, bb);
                    ldm4(bL, bb + 5120u);
                    mma16816p(accu[4*nb2+0], accu[4*nb2+1], aH, bH[0], bH[1]);
                    mma16816p(accu[4*nb2+0], accu[4*nb2+1], aH, bL[0], bL[1]);
                    mma16816p(accu[4*nb2+0], accu[4*nb2+1], aL, bH[0], bH[1]);
                    mma16816p(accu[4*nb2+2], accu[4*nb2+3], aH, bH[2], bH[3]);
                    mma16816p(accu[4*nb2+2], accu[4*nb2+3], aH, bL[2], bL[3]);
                    mma16816p(accu[4*nb2+2], accu[4*nb2+3], aL, bH[2], bH[3]);
                }
            }
        } else {
            // fma path: j 32..63, exact fp32 FFMA2
            const int fo = l & 7, isub = l >> 3;
            const char* pfb = base + SM_PF + (16 * wid + 4 * isub) * 144;
#pragma unroll
            for (int jb = 0; jb < 8; jb++) {
                float4 pr[4];
#pragma unroll
                for (int r = 0; r < 4; r++)
                    pr[r] = *(const float4*)(pfb + r * 144 + jb * 16);
#pragma unroll
                for (int jj = 0; jj < 4; jj++) {
                    const float* hrow = (const float*)(base + SM_HS) + (4 * jb + jj) * FF + 8 * fo;
                    unsigned long long h01, h23, h45, h67;
                    lds_u64x2(h01, h23, hrow);
                    lds_u64x2(h45, h67, hrow + 4);
#pragma unroll
                    for (int r = 0; r < 4; r++) {
                        float pvv = (jj == 0) ? pr[r].x : (jj == 1) ? pr[r].y :
                                    (jj == 2) ? pr[r].z : pr[r].w;
                        unsigned long long pp = pk2(pvv, pvv);
                        fma2(accu[4*r+0], pp, h01);
                        fma2(accu[4*r+1], pp, h23);
                        fma2(accu[4*r+2], pp, h45);
                        fma2(accu[4*r+3], pp, h67);
                    }
                }
            }
        }
    }
    CP_WAITALL();

    // z writeout (q1 lanes adjacent)
    zl += __shfl_xor_sync(0xffffffffu, zl, 1);
    zl += __shfl_xor_sync(0xffffffffu, zl, 2);
    if (q1 == 0) g_Z[split * NN + i0 + r1] = zl;

    // partial-sum writeout (disjoint buffers per pipe)
    if (wid >= 4) {
        const int iw = wid - 4, g = l >> 2, tig = l & 3;
#pragma unroll
        for (int nb = 0; nb < 8; nb++) {
            float2 v01 = upk(accu[2 * nb]), v23 = upk(accu[2 * nb + 1]);
            const int col = 8 * nb + 2 * tig;
            const int row = i0 + 16 * iw + g;
            *(float2*)&g_acc2[((size_t)split * NN + row) * FF + col]     = v01;
            *(float2*)&g_acc2[((size_t)split * NN + row + 8) * FF + col] = v23;
        }
    } else {
        const int fo = l & 7, isub = l >> 3;
#pragma unroll
        for (int r = 0; r < 4; r++) {
            const int row = i0 + 16 * wid + 4 * isub + r;
            float2 a0 = upk(accu[4*r]), a1 = upk(accu[4*r+1]);
            float2 a2 = upk(accu[4*r+2]), a3 = upk(accu[4*r+3]);
            float* dst = &g_acc[((size_t)split * NN + row) * FF + 8 * fo];
            *(float4*)dst       = make_float4(a0.x, a0.y, a1.x, a1.y);
            *(float4*)(dst + 4) = make_float4(a2.x, a2.y, a3.x, a3.y);
        }
    }
}

// ============ E: combine, normalize, ELU ============
__global__ void __launch_bounds__(256) k_combine(float* __restrict__ out) {
    const int idx = blockIdx.x * 256 + threadIdx.x;
    const int i = idx >> 6;
    float num = 0.f, den = 0.f;
#pragma unroll
    for (int s = 0; s < SPLITJ; s++) {
        num += g_acc[(size_t)s * NN * FF + idx] + g_acc2[(size_t)s * NN * FF + idx];
        den += g_Z[s * NN + i];
    }
    float r = num / den;
    out[idx] = (r > 0.0f) ? r : expm1f(r);
}

extern "C" void kernel_launch(void* const* d_in, const int* in_sizes, int n_in,
                              void* d_out, int out_size) {
    (void)in_sizes; (void)n_in; (void)out_size;
    const float* input  = (const float*)d_in[0];
    const float* W      = (const float*)d_in[1];
    const float* a      = (const float*)d_in[2];
    const float* W_si   = (const float*)d_in[3];
    const float* W_ei   = (const float*)d_in[4];
    const float* adj_ad = (const float*)d_in[5];
    const int*   adj    = (const int*)d_in[6];
    float* out = (float*)d_out;

    cudaFuncSetAttribute(k_attn, cudaFuncAttributeMaxDynamicSharedMemorySize, SM_BYTES);

    k_gemm_h<<<NN / 64, 256>>>(input, W);
    k_hlr<<<NN / 256, 256>>>(a);
    k_scalars<<<1, 256>>>(W_si, W_ei);
    k_prep_ht<<<NN / 64, 256>>>();
    k_attn<<<dim3(NN / BI, SPLITJ), 256, SM_BYTES>>>(adj_ad, adj);
    k_combine<<<NN * FF / 256, 256>>>(out);
}

// round 10
// speedup vs baseline: 1.3383x; 1.3383x over previous
#include <cuda_runtime.h>
#include <math.h>
#include <stdint.h>

#define NN 8192
#define KK 512
#define FF 64
#define SPLITJ 16
#define JCHUNK (NN / SPLITJ)   // 512
#define BI 64
#define BJ 64
#define NT (JCHUNK / BJ)       // 8

// smem layout (bytes), 16B-aligned base
#define ADSTG 17408            // 64 rows * 272B (68-float padded stride)
#define SM_AD 0                // 2 stages
#define SM_AJ (SM_AD + 2 * ADSTG)
#define SM_P  (SM_AJ + 2 * ADSTG)   // Phi 9216 + Plo 9216 (144B row stride)
#define SM_HT (SM_P + 2 * 9216)     // Hthi 9216 + Htlo 9216
#define SM_HR (SM_HT + 2 * 9216)    // 4096 (only 2048 used)
#define SM_BYTES (SM_HR + 4096)     // 110592

__device__ float g_h[(size_t)NN * FF];
__device__ float g_hl[NN];
__device__ float g_hr[NN];
__device__ float g_scalars[4];
__device__ uint32_t g_hT[2u * 64u * 4096u];          // [var][f][j/2] bf16x2, 2 MB
__device__ float g_acc[(size_t)SPLITJ * NN * FF];    // 32 MB
__device__ float g_Z[SPLITJ * NN];

// ---------- helpers ----------
__device__ __forceinline__ unsigned long long pk2(float x, float y) {
    unsigned long long r; asm("mov.b64 %0, {%1,%2};" : "=l"(r) : "f"(x), "f"(y)); return r;
}
__device__ __forceinline__ void fma2(unsigned long long& d, unsigned long long a, unsigned long long b) {
    asm("fma.rn.f32x2 %0, %1, %2, %0;" : "+l"(d) : "l"(a), "l"(b));
}
__device__ __forceinline__ float2 upk(unsigned long long v) {
    float2 f; asm("mov.b64 {%0,%1}, %2;" : "=f"(f.x), "=f"(f.y) : "l"(v)); return f;
}
__device__ __forceinline__ uint32_t smem_u32(const void* p) {
    uint32_t a; asm("{ .reg .u64 t; cvta.to.shared.u64 t, %1; cvt.u32.u64 %0, t; }" : "=r"(a) : "l"(p)); return a;
}
__device__ __forceinline__ void cpa16(uint32_t dst, const void* src) {
    asm volatile("cp.async.cg.shared.global [%0], [%1], 16;" :: "r"(dst), "l"(src));
}
#define CP_COMMIT()  asm volatile("cp.async.commit_group;" ::: "memory")
#define CP_WAIT1()   asm volatile("cp.async.wait_group 1;" ::: "memory")
#define CP_WAITALL() asm volatile("cp.async.wait_all;" ::: "memory")

__device__ __forceinline__ uint32_t bf16x2_of(float lo, float hi) {
    uint32_t r; asm("cvt.rn.bf16x2.f32 %0, %1, %2;" : "=r"(r) : "f"(hi), "f"(lo)); return r;
}
__device__ __forceinline__ void ldm4(uint32_t* r, uint32_t addr) {
    asm volatile("ldmatrix.sync.aligned.m8n8.x4.shared.b16 {%0,%1,%2,%3}, [%4];"
                 : "=r"(r[0]), "=r"(r[1]), "=r"(r[2]), "=r"(r[3]) : "r"(addr));
}
__device__ __forceinline__ void mma16816(float* d, const uint32_t* a, uint32_t b0, uint32_t b1) {
    asm("mma.sync.aligned.m16n8k16.row.col.f32.bf16.bf16.f32 "
        "{%0,%1,%2,%3}, {%4,%5,%6,%7}, {%8,%9}, {%0,%1,%2,%3};"
        : "+f"(d[0]), "+f"(d[1]), "+f"(d[2]), "+f"(d[3])
        : "r"(a[0]), "r"(a[1]), "r"(a[2]), "r"(a[3]), "r"(b0), "r"(b1));
}

// ============ A: h = input @ W ============
__global__ void __launch_bounds__(256) k_gemm_h(const float* __restrict__ X, const float* __restrict__ W) {
    __shared__ float xs[32][68];
    const int t = threadIdx.x, tx = t & 15, ty = t >> 4, i0 = blockIdx.x * 64;
    unsigned long long acc[4][2];
#pragma unroll
    for (int r = 0; r < 4; r++) { acc[r][0] = 0ULL; acc[r][1] = 0ULL; }
    for (int c0 = 0; c0 < KK; c0 += 32) {
#pragma unroll
        for (int q = 0; q < 8; q++) {
            int lin = t + 256 * q, row = lin >> 5, kk = lin & 31;
            xs[kk][row] = X[(size_t)(i0 + row) * KK + c0 + kk];
        }
        __syncthreads();
#pragma unroll
        for (int kk = 0; kk < 32; kk++) {
            float4 w4 = *(const float4*)&W[(size_t)(c0 + kk) * FF + 4 * tx];
            unsigned long long w01 = pk2(w4.x, w4.y), w23 = pk2(w4.z, w4.w);
            float4 a4 = *(const float4*)&xs[kk][4 * ty];
            float av[4] = {a4.x, a4.y, a4.z, a4.w};
#pragma unroll
            for (int r = 0; r < 4; r++) {
                unsigned long long ar = pk2(av[r], av[r]);
                fma2(acc[r][0], ar, w01); fma2(acc[r][1], ar, w23);
            }
        }
        __syncthreads();
    }
#pragma unroll
    for (int r = 0; r < 4; r++) {
        float2 lo = upk(acc[r][0]), hi = upk(acc[r][1]);
        *(float4*)&g_h[(size_t)(i0 + 4 * ty + r) * FF + 4 * tx] = make_float4(lo.x, lo.y, hi.x, hi.y);
    }
}

// ============ B: hl/hr ============
__global__ void __launch_bounds__(256) k_hlr(const float* __restrict__ a) {
    __shared__ float a1s[FF], a2s[FF];
    const int t = threadIdx.x;
    if (t < FF) a1s[t] = a[t]; else if (t < 2 * FF) a2s[t - FF] = a[t];
    __syncthreads();
    const int row = blockIdx.x * 256 + t;
    float s1 = 0.f, s2 = 0.f;
#pragma unroll
    for (int q = 0; q < 16; q++) {
        float4 h4 = *(const float4*)&g_h[(size_t)row * FF + 4 * q];
        s1 = fmaf(h4.x, a1s[4*q], fmaf(h4.y, a1s[4*q+1], fmaf(h4.z, a1s[4*q+2], fmaf(h4.w, a1s[4*q+3], s1))));
        s2 = fmaf(h4.x, a2s[4*q], fmaf(h4.y, a2s[4*q+1], fmaf(h4.z, a2s[4*q+2], fmaf(h4.w, a2s[4*q+3], s2))));
    }
    g_hl[row] = s1; g_hr[row] = s2;
}

// ============ C: scalars ============
__global__ void k_scalars(const float* __restrict__ Wsi, const float* __restrict__ Wei) {
    __shared__ float red[256];
    const int t = threadIdx.x;
    float m = -3.4e38f;
    for (int i = t; i < NN; i += 256) m = fmaxf(m, g_hr[i]);
    red[t] = m; __syncthreads();
    for (int s = 128; s > 0; s >>= 1) { if (t < s) red[t] = fmaxf(red[t], red[t + s]); __syncthreads(); }
    if (t == 0) { g_scalars[0] = red[0]; g_scalars[1] = fabsf(Wei[0]); g_scalars[2] = fabsf(Wsi[0]); }
}

// ============ Prep: H^T as [f][j] bf16 hi/lo ============
__global__ void __launch_bounds__(256) k_prep_ht() {
    __shared__ float hs[128 * 68];
    const int t = threadIdx.x, j0 = blockIdx.x * 128;
#pragma unroll
    for (int k = 0; k < 8; k++) {
        int i4 = k * 256 + t;
        int j = i4 >> 4, f4 = i4 & 15;
        *(float4*)&hs[j * 68 + f4 * 4] = *(const float4*)&g_h[(size_t)(j0 + j) * FF + f4 * 4];
    }
    __syncthreads();
    const int f = t >> 2, jq = t & 3;
#pragma unroll
    for (int m = 0; m < 4; m++) {
        int jl = jq * 32 + m * 8;
        uint32_t hiv[4], lov[4];
#pragma unroll
        for (int s = 0; s < 4; s++) {
            float v0 = hs[(jl + 2 * s) * 68 + f], v1 = hs[(jl + 2 * s + 1) * 68 + f];
            uint32_t h2 = bf16x2_of(v0, v1);
            hiv[s] = h2;
            lov[s] = bf16x2_of(v0 - __uint_as_float(h2 << 16), v1 - __uint_as_float(h2 & 0xffff0000u));
        }
        uint32_t idx = (uint32_t)f * 4096u + (uint32_t)((j0 + jl) >> 1);
        *(uint4*)&g_hT[idx]           = make_uint4(hiv[0], hiv[1], hiv[2], hiv[3]);
        *(uint4*)&g_hT[262144u + idx] = make_uint4(lov[0], lov[1], lov[2], lov[3]);
    }
}

// ============ D: fused attention (mma.sync, interleaved accumulators) ============
__device__ __forceinline__ void issue_adaj(const float* __restrict__ adj_ad, const int* __restrict__ adj,
                                           int i0, int j0, int t, uint32_t ad_dst, uint32_t aj_dst) {
#pragma unroll
    for (int k = 0; k < 4; k++) {
        int c = k * 256 + t, r = c >> 4, ch = c & 15;
        cpa16(ad_dst + r * 272 + ch * 16, adj_ad + (size_t)(i0 + r) * NN + j0 + ch * 4);
        cpa16(aj_dst + r * 272 + ch * 16, adj    + (size_t)(i0 + r) * NN + j0 + ch * 4);
    }
}

__global__ void __launch_bounds__(256, 2) k_attn(const float* __restrict__ adj_ad,
                                                 const int* __restrict__ adj) {
    extern __shared__ float4 smem4[];
    char* base = (char*)smem4;
    const uint32_t sb = smem_u32(base);

    const int t = threadIdx.x, wid = t >> 5, l = t & 31;
    const int i0 = blockIdx.x * BI, split = blockIdx.y, j0b = split * JCHUNK;

    if (t < 128) *(float4*)(base + SM_HR + 16 * t) = *(const float4*)&g_hr[j0b + 4 * t];

    const float hrmax = g_scalars[0], wei = g_scalars[1], wsi = g_scalars[2];
    const int r1 = t >> 2, q1 = t & 3;
    const float hl_r = g_hl[i0 + r1];
    float smax = hl_r + hrmax;
    const float m_r = fmaf(wei, fmaxf(smax, 0.2f * smax), wsi);

    const int iw = wid & 3, fh = wid >> 2;
    const uint32_t aRow = (uint32_t)((l & 7) | (l & 8));
    const uint32_t aOff = (uint32_t)(16 * iw + aRow) * 144u + (uint32_t)(((l >> 4) & 1) * 16);
    const uint32_t bRow = (uint32_t)(32 * fh + ((l & 7) | (((l >> 4) & 1) << 3)));
    const uint32_t bOff = bRow * 144u + (uint32_t)(((l >> 3) & 1) * 16);
    const uint32_t pHi = sb + SM_P + aOff,  pLo = pHi + 9216u;
    const uint32_t hH0 = sb + SM_HT + bOff, hH1 = hH0 + 16u * 144u;
    const uint32_t hL0 = hH0 + 9216u,       hL1 = hH1 + 9216u;

    float acc[16];
#pragma unroll
    for (int i = 0; i < 16; i++) acc[i] = 0.f;
    float zl = 0.f;

    issue_adaj(adj_ad, adj, i0, j0b, t, sb + SM_AD, sb + SM_AJ);
    CP_COMMIT();
    uint4 hreg[4];
#pragma unroll
    for (int k = 0; k < 4; k++) {
        int c = k * 256 + t, var = c >> 9, f = (c >> 3) & 63, ch = c & 7;
        hreg[k] = *(const uint4*)&g_hT[(uint32_t)var * 262144u + (uint32_t)f * 4096u +
                                       (uint32_t)(j0b >> 1) + (uint32_t)ch * 4u];
    }

    for (int jt = 0; jt < NT; jt++) {
        const int cst = jt & 1, nst = (jt + 1) & 1;
        const int jn = (jt + 1 < NT) ? jt + 1 : NT - 1;
        issue_adaj(adj_ad, adj, i0, j0b + jn * BJ, t, sb + SM_AD + nst * ADSTG, sb + SM_AJ + nst * ADSTG);
        CP_COMMIT();
        CP_WAIT1();
        __syncthreads();   // adaj[jt] visible; phase2[jt-1] done with P/Ht

        // ---- phase 1: p + bf16 split ----
        {
            const float* ads = (const float*)(base + SM_AD + cst * ADSTG) + r1 * 68 + q1 * 16;
            const int*   ajs = (const int*)  (base + SM_AJ + cst * ADSTG) + r1 * 68 + q1 * 16;
            const float* hrs = (const float*)(base + SM_HR) + jt * 64 + q1 * 16;
            uint32_t hiv[8], lov[8];
#pragma unroll
            for (int k = 0; k < 4; k++) {
                float4 ad4 = *(const float4*)(ads + 4 * k);
                int4   aj4 = *(const int4*)(ajs + 4 * k);
                float4 hr4 = *(const float4*)(hrs + 4 * k);
                float pv[4];
                {
                    float s = hl_r + hr4.x, lr = fmaxf(s, 0.2f * s);
                    pv[0] = (aj4.x > 0) ? __expf(fmaf(wei, lr, fmaf(wsi, ad4.x, -m_r))) : 0.f;
                }
                {
                    float s = hl_r + hr4.y, lr = fmaxf(s, 0.2f * s);
                    pv[1] = (aj4.y > 0) ? __expf(fmaf(wei, lr, fmaf(wsi, ad4.y, -m_r))) : 0.f;
                }
                {
                    float s = hl_r + hr4.z, lr = fmaxf(s, 0.2f * s);
                    pv[2] = (aj4.z > 0) ? __expf(fmaf(wei, lr, fmaf(wsi, ad4.z, -m_r))) : 0.f;
                }
                {
                    float s = hl_r + hr4.w, lr = fmaxf(s, 0.2f * s);
                    pv[3] = (aj4.w > 0) ? __expf(fmaf(wei, lr, fmaf(wsi, ad4.w, -m_r))) : 0.f;
                }
                zl += (pv[0] + pv[1]) + (pv[2] + pv[3]);
                uint32_t h0 = bf16x2_of(pv[0], pv[1]);
                uint32_t h1 = bf16x2_of(pv[2], pv[3]);
                hiv[2*k]   = h0;
                hiv[2*k+1] = h1;
                lov[2*k]   = bf16x2_of(pv[0] - __uint_as_float(h0 << 16), pv[1] - __uint_as_float(h0 & 0xffff0000u));
                lov[2*k+1] = bf16x2_of(pv[2] - __uint_as_float(h1 << 16), pv[3] - __uint_as_float(h1 & 0xffff0000u));
            }
            char* pb = base + SM_P + r1 * 144 + q1 * 32;
            *(uint4*)pb          = make_uint4(hiv[0], hiv[1], hiv[2], hiv[3]);
            *(uint4*)(pb + 16)   = make_uint4(hiv[4], hiv[5], hiv[6], hiv[7]);
            *(uint4*)(pb + 9216) = make_uint4(lov[0], lov[1], lov[2], lov[3]);
            *(uint4*)(pb + 9232) = make_uint4(lov[4], lov[5], lov[6], lov[7]);
        }

        // ---- stage Ht[jt] from regs, prefetch Ht[jt+1] ----
#pragma unroll
        for (int k = 0; k < 4; k++) {
            int c = k * 256 + t, var = c >> 9, f = (c >> 3) & 63, ch = c & 7;
            *(uint4*)(base + SM_HT + var * 9216 + f * 144 + ch * 16) = hreg[k];
        }
        if (jt + 1 < NT) {
#pragma unroll
            for (int k = 0; k < 4; k++) {
                int c = k * 256 + t, var = c >> 9, f = (c >> 3) & 63, ch = c & 7;
                hreg[k] = *(const uint4*)&g_hT[(uint32_t)var * 262144u + (uint32_t)f * 4096u +
                                               (uint32_t)((j0b + (jt + 1) * BJ) >> 1) + (uint32_t)ch * 4u];
            }
        }
        __syncthreads();   // P + Ht ready

        // ---- phase 2: mma, accumulators interleaved 4-apart ----
#pragma unroll
        for (int ks = 0; ks < 4; ks++) {
            const uint32_t ka = (uint32_t)ks * 32u;
            uint32_t ahi[4], alo[4], bh0[4], bh1[4], bl0[4], bl1[4];
            ldm4(ahi, pHi + ka);
            ldm4(bh0, hH0 + ka);
            ldm4(bh1, hH1 + ka);
            ldm4(alo, pLo + ka);
            ldm4(bl0, hL0 + ka);
            ldm4(bl1, hL1 + ka);
            // round 1: ahi x bhX
            mma16816(acc + 0,  ahi, bh0[0], bh0[1]);
            mma16816(acc + 4,  ahi, bh0[2], bh0[3]);
            mma16816(acc + 8,  ahi, bh1[0], bh1[1]);
            mma16816(acc + 12, ahi, bh1[2], bh1[3]);
            // round 2: ahi x blX
            mma16816(acc + 0,  ahi, bl0[0], bl0[1]);
            mma16816(acc + 4,  ahi, bl0[2], bl0[3]);
            mma16816(acc + 8,  ahi, bl1[0], bl1[1]);
            mma16816(acc + 12, ahi, bl1[2], bl1[3]);
            // round 3: alo x bhX
            mma16816(acc + 0,  alo, bh0[0], bh0[1]);
            mma16816(acc + 4,  alo, bh0[2], bh0[3]);
            mma16816(acc + 8,  alo, bh1[0], bh1[1]);
            mma16816(acc + 12, alo, bh1[2], bh1[3]);
        }
    }
    CP_WAITALL();

    // z writeout
    zl += __shfl_xor_sync(0xffffffffu, zl, 1);
    zl += __shfl_xor_sync(0xffffffffu, zl, 2);
    if (q1 == 0) g_Z[split * NN + i0 + r1] = zl;

    // acc writeout
    {
        const int g = l >> 2, tig = l & 3;
#pragma unroll
        for (int nt = 0; nt < 4; nt++) {
            const int col = 32 * fh + 8 * nt + 2 * tig;
            const size_t b0 = ((size_t)split * NN + i0 + 16 * iw + g) * FF + col;
            const size_t b1 = b0 + (size_t)8 * FF;
            *(float2*)&g_acc[b0] = make_float2(acc[4 * nt + 0], acc[4 * nt + 1]);
            *(float2*)&g_acc[b1] = make_float2(acc[4 * nt + 2], acc[4 * nt + 3]);
        }
    }
}

// ============ E: combine, normalize, ELU ============
__global__ void __launch_bounds__(256) k_combine(float* __restrict__ out) {
    const int idx = blockIdx.x * 256 + threadIdx.x;
    const int i = idx >> 6;
    float num = 0.f, den = 0.f;
#pragma unroll
    for (int s = 0; s < SPLITJ; s++) {
        num += g_acc[(size_t)s * NN * FF + idx];
        den += g_Z[s * NN + i];
    }
    float r = num / den;
    out[idx] = (r > 0.0f) ? r : expm1f(r);
}

extern "C" void kernel_launch(void* const* d_in, const int* in_sizes, int n_in,
                              void* d_out, int out_size) {
    (void)in_sizes; (void)n_in; (void)out_size;
    const float* input  = (const float*)d_in[0];
    const float* W      = (const float*)d_in[1];
    const float* a      = (const float*)d_in[2];
    const float* W_si   = (const float*)d_in[3];
    const float* W_ei   = (const float*)d_in[4];
    const float* adj_ad = (const float*)d_in[5];
    const int*   adj    = (const int*)d_in[6];
    float* out = (float*)d_out;

    cudaFuncSetAttribute(k_attn, cudaFuncAttributeMaxDynamicSharedMemorySize, SM_BYTES);

    k_gemm_h<<<NN / 64, 256>>>(input, W);
    k_hlr<<<NN / 256, 256>>>(a);
    k_scalars<<<1, 256>>>(W_si, W_ei);
    k_prep_ht<<<NN / 128, 256>>>();
    k_attn<<<dim3(NN / BI, SPLITJ), 256, SM_BYTES>>>(adj_ad, adj);
    k_combine<<<NN * FF / 256, 256>>>(out);
}

// round 11
// speedup vs baseline: 1.4078x; 1.0519x over previous
#include <cuda_runtime.h>
#include <cuda_fp16.h>
#include <math.h>
#include <stdint.h>

#define NN 8192
#define KK 512
#define FF 64
#define SPLITJ 16
#define JCHUNK (NN / SPLITJ)   // 512
#define BI 64
#define BJ 64
#define NT (JCHUNK / BJ)       // 8

// smem layout (bytes), 16B-aligned base
#define ADSTG 17408            // 64 rows * 272B (68-float padded stride)
#define SM_AD 0                // 2 stages
#define SM_AJ (SM_AD + 2 * ADSTG)
#define SM_P  (SM_AJ + 2 * ADSTG)   // P fp16, single plane, 144B row stride: 9216
#define SM_HT (SM_P + 9216)         // Ht fp16: hi 9216 + lo 9216
#define SM_HR (SM_HT + 2 * 9216)    // 4096 (2048 used)
#define SM_BYTES (SM_HR + 4096)     // 101376

__device__ float g_h[(size_t)NN * FF];
__device__ float g_hl[NN];
__device__ float g_hr[NN];
__device__ float g_scalars[4];
__device__ uint32_t g_hT[2u * 64u * 4096u];          // [var][f][j/2] f16x2, 2 MB
__device__ float g_acc[(size_t)SPLITJ * NN * FF];    // 32 MB
__device__ float g_Z[SPLITJ * NN];

// ---------- helpers ----------
__device__ __forceinline__ unsigned long long pk2(float x, float y) {
    unsigned long long r; asm("mov.b64 %0, {%1,%2};" : "=l"(r) : "f"(x), "f"(y)); return r;
}
__device__ __forceinline__ void fma2(unsigned long long& d, unsigned long long a, unsigned long long b) {
    asm("fma.rn.f32x2 %0, %1, %2, %0;" : "+l"(d) : "l"(a), "l"(b));
}
__device__ __forceinline__ float2 upk(unsigned long long v) {
    float2 f; asm("mov.b64 {%0,%1}, %2;" : "=f"(f.x), "=f"(f.y) : "l"(v)); return f;
}
__device__ __forceinline__ uint32_t smem_u32(const void* p) {
    uint32_t a; asm("{ .reg .u64 t; cvta.to.shared.u64 t, %1; cvt.u32.u64 %0, t; }" : "=r"(a) : "l"(p)); return a;
}
__device__ __forceinline__ void cpa16(uint32_t dst, const void* src) {
    asm volatile("cp.async.cg.shared.global [%0], [%1], 16;" :: "r"(dst), "l"(src));
}
#define CP_COMMIT()  asm volatile("cp.async.commit_group;" ::: "memory")
#define CP_WAIT1()   asm volatile("cp.async.wait_group 1;" ::: "memory")
#define CP_WAITALL() asm volatile("cp.async.wait_all;" ::: "memory")

__device__ __forceinline__ uint32_t f16x2_of(float lo, float hi) {
    uint32_t r; asm("cvt.rn.f16x2.f32 %0, %1, %2;" : "=r"(r) : "f"(hi), "f"(lo)); return r;
}
__device__ __forceinline__ float lo_h2f(uint32_t h2) {
    float f; asm("{.reg .f16 a,b; mov.b32 {a,b}, %1; cvt.f32.f16 %0, a;}" : "=f"(f) : "r"(h2)); return f;
}
__device__ __forceinline__ float hi_h2f(uint32_t h2) {
    float f; asm("{.reg .f16 a,b; mov.b32 {a,b}, %1; cvt.f32.f16 %0, b;}" : "=f"(f) : "r"(h2)); return f;
}
__device__ __forceinline__ void ldm4(uint32_t* r, uint32_t addr) {
    asm volatile("ldmatrix.sync.aligned.m8n8.x4.shared.b16 {%0,%1,%2,%3}, [%4];"
                 : "=r"(r[0]), "=r"(r[1]), "=r"(r[2]), "=r"(r[3]) : "r"(addr));
}
__device__ __forceinline__ void mma16816(float* d, const uint32_t* a, uint32_t b0, uint32_t b1) {
    asm("mma.sync.aligned.m16n8k16.row.col.f32.f16.f16.f32 "
        "{%0,%1,%2,%3}, {%4,%5,%6,%7}, {%8,%9}, {%0,%1,%2,%3};"
        : "+f"(d[0]), "+f"(d[1]), "+f"(d[2]), "+f"(d[3])
        : "r"(a[0]), "r"(a[1]), "r"(a[2]), "r"(a[3]), "r"(b0), "r"(b1));
}

// ============ A: h = input @ W ============
__global__ void __launch_bounds__(256) k_gemm_h(const float* __restrict__ X, const float* __restrict__ W) {
    __shared__ float xs[32][68];
    const int t = threadIdx.x, tx = t & 15, ty = t >> 4, i0 = blockIdx.x * 64;
    unsigned long long acc[4][2];
#pragma unroll
    for (int r = 0; r < 4; r++) { acc[r][0] = 0ULL; acc[r][1] = 0ULL; }
    for (int c0 = 0; c0 < KK; c0 += 32) {
#pragma unroll
        for (int q = 0; q < 8; q++) {
            int lin = t + 256 * q, row = lin >> 5, kk = lin & 31;
            xs[kk][row] = X[(size_t)(i0 + row) * KK + c0 + kk];
        }
        __syncthreads();
#pragma unroll
        for (int kk = 0; kk < 32; kk++) {
            float4 w4 = *(const float4*)&W[(size_t)(c0 + kk) * FF + 4 * tx];
            unsigned long long w01 = pk2(w4.x, w4.y), w23 = pk2(w4.z, w4.w);
            float4 a4 = *(const float4*)&xs[kk][4 * ty];
            float av[4] = {a4.x, a4.y, a4.z, a4.w};
#pragma unroll
            for (int r = 0; r < 4; r++) {
                unsigned long long ar = pk2(av[r], av[r]);
                fma2(acc[r][0], ar, w01); fma2(acc[r][1], ar, w23);
            }
        }
        __syncthreads();
    }
#pragma unroll
    for (int r = 0; r < 4; r++) {
        float2 lo = upk(acc[r][0]), hi = upk(acc[r][1]);
        *(float4*)&g_h[(size_t)(i0 + 4 * ty + r) * FF + 4 * tx] = make_float4(lo.x, lo.y, hi.x, hi.y);
    }
}

// ============ B: hl/hr ============
__global__ void __launch_bounds__(256) k_hlr(const float* __restrict__ a) {
    __shared__ float a1s[FF], a2s[FF];
    const int t = threadIdx.x;
    if (t < FF) a1s[t] = a[t]; else if (t < 2 * FF) a2s[t - FF] = a[t];
    __syncthreads();
    const int row = blockIdx.x * 256 + t;
    float s1 = 0.f, s2 = 0.f;
#pragma unroll
    for (int q = 0; q < 16; q++) {
        float4 h4 = *(const float4*)&g_h[(size_t)row * FF + 4 * q];
        s1 = fmaf(h4.x, a1s[4*q], fmaf(h4.y, a1s[4*q+1], fmaf(h4.z, a1s[4*q+2], fmaf(h4.w, a1s[4*q+3], s1))));
        s2 = fmaf(h4.x, a2s[4*q], fmaf(h4.y, a2s[4*q+1], fmaf(h4.z, a2s[4*q+2], fmaf(h4.w, a2s[4*q+3], s2))));
    }
    g_hl[row] = s1; g_hr[row] = s2;
}

// ============ C: scalars ============
__global__ void k_scalars(const float* __restrict__ Wsi, const float* __restrict__ Wei) {
    __shared__ float red[256];
    const int t = threadIdx.x;
    float m = -3.4e38f;
    for (int i = t; i < NN; i += 256) m = fmaxf(m, g_hr[i]);
    red[t] = m; __syncthreads();
    for (int s = 128; s > 0; s >>= 1) { if (t < s) red[t] = fmaxf(red[t], red[t + s]); __syncthreads(); }
    if (t == 0) { g_scalars[0] = red[0]; g_scalars[1] = fabsf(Wei[0]); g_scalars[2] = fabsf(Wsi[0]); }
}

// ============ Prep: H^T as [f][j] fp16 hi/lo ============
__global__ void __launch_bounds__(256) k_prep_ht() {
    __shared__ float hs[128 * 68];
    const int t = threadIdx.x, j0 = blockIdx.x * 128;
#pragma unroll
    for (int k = 0; k < 8; k++) {
        int i4 = k * 256 + t;
        int j = i4 >> 4, f4 = i4 & 15;
        *(float4*)&hs[j * 68 + f4 * 4] = *(const float4*)&g_h[(size_t)(j0 + j) * FF + f4 * 4];
    }
    __syncthreads();
    const int f = t >> 2, jq = t & 3;
#pragma unroll
    for (int m = 0; m < 4; m++) {
        int jl = jq * 32 + m * 8;
        uint32_t hiv[4], lov[4];
#pragma unroll
        for (int s = 0; s < 4; s++) {
            float v0 = hs[(jl + 2 * s) * 68 + f], v1 = hs[(jl + 2 * s + 1) * 68 + f];
            uint32_t h2 = f16x2_of(v0, v1);
            hiv[s] = h2;
            lov[s] = f16x2_of(v0 - lo_h2f(h2), v1 - hi_h2f(h2));
        }
        uint32_t idx = (uint32_t)f * 4096u + (uint32_t)((j0 + jl) >> 1);
        *(uint4*)&g_hT[idx]           = make_uint4(hiv[0], hiv[1], hiv[2], hiv[3]);
        *(uint4*)&g_hT[262144u + idx] = make_uint4(lov[0], lov[1], lov[2], lov[3]);
    }
}

// ============ D: fused attention (fp16 2-term mma) ============
__device__ __forceinline__ void issue_adaj(const float* __restrict__ adj_ad, const int* __restrict__ adj,
                                           int i0, int j0, int t, uint32_t ad_dst, uint32_t aj_dst) {
#pragma unroll
    for (int k = 0; k < 4; k++) {
        int c = k * 256 + t, r = c >> 4, ch = c & 15;
        cpa16(ad_dst + r * 272 + ch * 16, adj_ad + (size_t)(i0 + r) * NN + j0 + ch * 4);
        cpa16(aj_dst + r * 272 + ch * 16, adj    + (size_t)(i0 + r) * NN + j0 + ch * 4);
    }
}

__global__ void __launch_bounds__(256, 2) k_attn(const float* __restrict__ adj_ad,
                                                 const int* __restrict__ adj) {
    extern __shared__ float4 smem4[];
    char* base = (char*)smem4;
    const uint32_t sb = smem_u32(base);

    const int t = threadIdx.x, wid = t >> 5, l = t & 31;
    const int i0 = blockIdx.x * BI, split = blockIdx.y, j0b = split * JCHUNK;

    if (t < 128) *(float4*)(base + SM_HR + 16 * t) = *(const float4*)&g_hr[j0b + 4 * t];

    const float hrmax = g_scalars[0], wei = g_scalars[1], wsi = g_scalars[2];
    const int r1 = t >> 2, q1 = t & 3;
    const float hl_r = g_hl[i0 + r1];
    float smax = hl_r + hrmax;
    const float m_r = fmaf(wei, fmaxf(smax, 0.2f * smax), wsi);

    const int iw = wid & 3, fh = wid >> 2;
    const uint32_t aRow = (uint32_t)((l & 7) | (l & 8));
    const uint32_t aOff = (uint32_t)(16 * iw + aRow) * 144u + (uint32_t)(((l >> 4) & 1) * 16);
    const uint32_t bRow = (uint32_t)(32 * fh + ((l & 7) | (((l >> 4) & 1) << 3)));
    const uint32_t bOff = bRow * 144u + (uint32_t)(((l >> 3) & 1) * 16);
    const uint32_t pA  = sb + SM_P + aOff;
    const uint32_t hH0 = sb + SM_HT + bOff, hH1 = hH0 + 16u * 144u;
    const uint32_t hL0 = hH0 + 9216u,       hL1 = hH1 + 9216u;

    float acc[16];
#pragma unroll
    for (int i = 0; i < 16; i++) acc[i] = 0.f;
    float zl = 0.f;

    issue_adaj(adj_ad, adj, i0, j0b, t, sb + SM_AD, sb + SM_AJ);
    CP_COMMIT();
    uint4 hreg[4];
#pragma unroll
    for (int k = 0; k < 4; k++) {
        int c = k * 256 + t, var = c >> 9, f = (c >> 3) & 63, ch = c & 7;
        hreg[k] = *(const uint4*)&g_hT[(uint32_t)var * 262144u + (uint32_t)f * 4096u +
                                       (uint32_t)(j0b >> 1) + (uint32_t)ch * 4u];
    }

    for (int jt = 0; jt < NT; jt++) {
        const int cst = jt & 1, nst = (jt + 1) & 1;
        const int jn = (jt + 1 < NT) ? jt + 1 : NT - 1;
        issue_adaj(adj_ad, adj, i0, j0b + jn * BJ, t, sb + SM_AD + nst * ADSTG, sb + SM_AJ + nst * ADSTG);
        CP_COMMIT();
        CP_WAIT1();
        __syncthreads();   // adaj[jt] visible; phase2[jt-1] done with P/Ht

        // ---- phase 1: p -> fp16 ----
        {
            const float* ads = (const float*)(base + SM_AD + cst * ADSTG) + r1 * 68 + q1 * 16;
            const int*   ajs = (const int*)  (base + SM_AJ + cst * ADSTG) + r1 * 68 + q1 * 16;
            const float* hrs = (const float*)(base + SM_HR) + jt * 64 + q1 * 16;
            uint32_t pw[8];
#pragma unroll
            for (int k = 0; k < 4; k++) {
                float4 ad4 = *(const float4*)(ads + 4 * k);
                int4   aj4 = *(const int4*)(ajs + 4 * k);
                float4 hr4 = *(const float4*)(hrs + 4 * k);
                float pv[4];
                {
                    float s = hl_r + hr4.x, lr = fmaxf(s, 0.2f * s);
                    pv[0] = (aj4.x > 0) ? __expf(fmaf(wei, lr, fmaf(wsi, ad4.x, -m_r))) : 0.f;
                }
                {
                    float s = hl_r + hr4.y, lr = fmaxf(s, 0.2f * s);
                    pv[1] = (aj4.y > 0) ? __expf(fmaf(wei, lr, fmaf(wsi, ad4.y, -m_r))) : 0.f;
                }
                {
                    float s = hl_r + hr4.z, lr = fmaxf(s, 0.2f * s);
                    pv[2] = (aj4.z > 0) ? __expf(fmaf(wei, lr, fmaf(wsi, ad4.z, -m_r))) : 0.f;
                }
                {
                    float s = hl_r + hr4.w, lr = fmaxf(s, 0.2f * s);
                    pv[3] = (aj4.w > 0) ? __expf(fmaf(wei, lr, fmaf(wsi, ad4.w, -m_r))) : 0.f;
                }
                zl += (pv[0] + pv[1]) + (pv[2] + pv[3]);
                pw[2*k]   = f16x2_of(pv[0], pv[1]);
                pw[2*k+1] = f16x2_of(pv[2], pv[3]);
            }
            char* pb = base + SM_P + r1 * 144 + q1 * 32;
            *(uint4*)pb        = make_uint4(pw[0], pw[1], pw[2], pw[3]);
            *(uint4*)(pb + 16) = make_uint4(pw[4], pw[5], pw[6], pw[7]);
        }

        // ---- stage Ht[jt] from regs, prefetch Ht[jt+1] ----
#pragma unroll
        for (int k = 0; k < 4; k++) {
            int c = k * 256 + t, var = c >> 9, f = (c >> 3) & 63, ch = c & 7;
            *(uint4*)(base + SM_HT + var * 9216 + f * 144 + ch * 16) = hreg[k];
        }
        if (jt + 1 < NT) {
#pragma unroll
            for (int k = 0; k < 4; k++) {
                int c = k * 256 + t, var = c >> 9, f = (c >> 3) & 63, ch = c & 7;
                hreg[k] = *(const uint4*)&g_hT[(uint32_t)var * 262144u + (uint32_t)f * 4096u +
                                               (uint32_t)((j0b + (jt + 1) * BJ) >> 1) + (uint32_t)ch * 4u];
            }
        }
        __syncthreads();   // P + Ht ready

        // ---- phase 2: 8 mma/ks, acc quads 4-apart ----
#pragma unroll
        for (int ks = 0; ks < 4; ks++) {
            const uint32_t ka = (uint32_t)ks * 32u;
            uint32_t ap[4], bh0[4], bh1[4], bl0[4], bl1[4];
            ldm4(ap,  pA  + ka);
            ldm4(bh0, hH0 + ka);
            ldm4(bh1, hH1 + ka);
            ldm4(bl0, hL0 + ka);
            ldm4(bl1, hL1 + ka);
            mma16816(acc + 0,  ap, bh0[0], bh0[1]);
            mma16816(acc + 4,  ap, bh0[2], bh0[3]);
            mma16816(acc + 8,  ap, bh1[0], bh1[1]);
            mma16816(acc + 12, ap, bh1[2], bh1[3]);
            mma16816(acc + 0,  ap, bl0[0], bl0[1]);
            mma16816(acc + 4,  ap, bl0[2], bl0[3]);
            mma16816(acc + 8,  ap, bl1[0], bl1[1]);
            mma16816(acc + 12, ap, bl1[2], bl1[3]);
        }
    }
    CP_WAITALL();

    // z writeout
    zl += __shfl_xor_sync(0xffffffffu, zl, 1);
    zl += __shfl_xor_sync(0xffffffffu, zl, 2);
    if (q1 == 0) g_Z[split * NN + i0 + r1] = zl;

    // acc writeout
    {
        const int g = l >> 2, tig = l & 3;
#pragma unroll
        for (int nt = 0; nt < 4; nt++) {
            const int col = 32 * fh + 8 * nt + 2 * tig;
            const size_t b0 = ((size_t)split * NN + i0 + 16 * iw + g) * FF + col;
            const size_t b1 = b0 + (size_t)8 * FF;
            *(float2*)&g_acc[b0] = make_float2(acc[4 * nt + 0], acc[4 * nt + 1]);
            *(float2*)&g_acc[b1] = make_float2(acc[4 * nt + 2], acc[4 * nt + 3]);
        }
    }
}

// ============ E: combine, normalize, ELU ============
__global__ void __launch_bounds__(256) k_combine(float* __restrict__ out) {
    const int idx = blockIdx.x * 256 + threadIdx.x;
    const int i = idx >> 6;
    float num = 0.f, den = 0.f;
#pragma unroll
    for (int s = 0; s < SPLITJ; s++) {
        num += g_acc[(size_t)s * NN * FF + idx];
        den += g_Z[s * NN + i];
    }
    float r = num / den;
    out[idx] = (r > 0.0f) ? r : expm1f(r);
}

extern "C" void kernel_launch(void* const* d_in, const int* in_sizes, int n_in,
                              void* d_out, int out_size) {
    (void)in_sizes; (void)n_in; (void)out_size;
    const float* input  = (const float*)d_in[0];
    const float* W      = (const float*)d_in[1];
    const float* a      = (const float*)d_in[2];
    const float* W_si   = (const float*)d_in[3];
    const float* W_ei   = (const float*)d_in[4];
    const float* adj_ad = (const float*)d_in[5];
    const int*   adj    = (const int*)d_in[6];
    float* out = (float*)d_out;

    cudaFuncSetAttribute(k_attn, cudaFuncAttributeMaxDynamicSharedMemorySize, SM_BYTES);

    k_gemm_h<<<NN / 64, 256>>>(input, W);
    k_hlr<<<NN / 256, 256>>>(a);
    k_scalars<<<1, 256>>>(W_si, W_ei);
    k_prep_ht<<<NN / 128, 256>>>();
    k_attn<<<dim3(NN / BI, SPLITJ), 256, SM_BYTES>>>(adj_ad, adj);
    k_combine<<<NN * FF / 256, 256>>>(out);
}

// round 12
// speedup vs baseline: 1.4605x; 1.0374x over previous
#include <cuda_runtime.h>
#include <cuda_fp16.h>
#include <math.h>
#include <stdint.h>

#define NN 8192
#define KK 512
#define FF 64
#define SPLITJ 16
#define JCHUNK (NN / SPLITJ)   // 512
#define BI 64
#define BJ 64
#define NT (JCHUNK / BJ)       // 8

// smem layout (bytes)
#define ADSTG 17408                  // 64 rows * 272B
#define SM_AD 0                      // 3 stages: 52224
#define SM_HT (3 * ADSTG)            // 4 stages x 9216 = 36864
#define SM_P  (SM_HT + 4 * 9216)     // fp16 P, 144B stride: 9216
#define SM_HR (SM_P + 9216)          // 2048
#define SM_BYTES (SM_HR + 2048)      // 100352

__device__ float g_h[(size_t)NN * FF];
__device__ float g_hl[NN];
__device__ float g_hr[NN];
__device__ float g_scalars[4];                        // [1]=|W_ei| [2]=|W_si|
__device__ unsigned g_hrmaxkey = 0u;                  // order-preserving float key
__device__ uint32_t g_hT[128u * 2048u];               // [tile][f][j/2] f16x2, 1 MB
__device__ float g_acc[(size_t)SPLITJ * NN * FF];     // 32 MB
__device__ float g_Z[SPLITJ * NN];

// ---------- helpers ----------
__device__ __forceinline__ unsigned long long pk2(float x, float y) {
    unsigned long long r; asm("mov.b64 %0, {%1,%2};" : "=l"(r) : "f"(x), "f"(y)); return r;
}
__device__ __forceinline__ void fma2(unsigned long long& d, unsigned long long a, unsigned long long b) {
    asm("fma.rn.f32x2 %0, %1, %2, %0;" : "+l"(d) : "l"(a), "l"(b));
}
__device__ __forceinline__ float2 upk(unsigned long long v) {
    float2 f; asm("mov.b64 {%0,%1}, %2;" : "=f"(f.x), "=f"(f.y) : "l"(v)); return f;
}
__device__ __forceinline__ uint32_t smem_u32(const void* p) {
    uint32_t a; asm("{ .reg .u64 t; cvta.to.shared.u64 t, %1; cvt.u32.u64 %0, t; }" : "=r"(a) : "l"(p)); return a;
}
__device__ __forceinline__ void cpa16(uint32_t dst, const void* src) {
    asm volatile("cp.async.cg.shared.global [%0], [%1], 16;" :: "r"(dst), "l"(src));
}
#define CP_COMMIT()  asm volatile("cp.async.commit_group;" ::: "memory")
#define CP_WAIT2()   asm volatile("cp.async.wait_group 2;" ::: "memory")
#define CP_WAITALL() asm volatile("cp.async.wait_all;" ::: "memory")

__device__ __forceinline__ uint32_t f16x2_of(float lo, float hi) {
    uint32_t r; asm("cvt.rn.f16x2.f32 %0, %1, %2;" : "=r"(r) : "f"(hi), "f"(lo)); return r;
}
__device__ __forceinline__ void ldm4(uint32_t* r, uint32_t addr) {
    asm volatile("ldmatrix.sync.aligned.m8n8.x4.shared.b16 {%0,%1,%2,%3}, [%4];"
                 : "=r"(r[0]), "=r"(r[1]), "=r"(r[2]), "=r"(r[3]) : "r"(addr));
}
__device__ __forceinline__ void mma16816(float* d, const uint32_t* a, uint32_t b0, uint32_t b1) {
    asm("mma.sync.aligned.m16n8k16.row.col.f32.f16.f16.f32 "
        "{%0,%1,%2,%3}, {%4,%5,%6,%7}, {%8,%9}, {%0,%1,%2,%3};"
        : "+f"(d[0]), "+f"(d[1]), "+f"(d[2]), "+f"(d[3])
        : "r"(a[0]), "r"(a[1]), "r"(a[2]), "r"(a[3]), "r"(b0), "r"(b1));
}
__device__ __forceinline__ unsigned fkey(float f) {
    unsigned u = __float_as_uint(f);
    return (u & 0x80000000u) ? ~u : (u | 0x80000000u);
}
__device__ __forceinline__ float fkeyinv(unsigned k) {
    unsigned u = (k & 0x80000000u) ? (k ^ 0x80000000u) : ~k;
    return __uint_as_float(u);
}

// ============ A: h = input @ W ============
__global__ void __launch_bounds__(256) k_gemm_h(const float* __restrict__ X, const float* __restrict__ W) {
    __shared__ float xs[32][68];
    const int t = threadIdx.x, tx = t & 15, ty = t >> 4, i0 = blockIdx.x * 64;
    unsigned long long acc[4][2];
#pragma unroll
    for (int r = 0; r < 4; r++) { acc[r][0] = 0ULL; acc[r][1] = 0ULL; }
    for (int c0 = 0; c0 < KK; c0 += 32) {
#pragma unroll
        for (int q = 0; q < 8; q++) {
            int lin = t + 256 * q, row = lin >> 5, kk = lin & 31;
            xs[kk][row] = X[(size_t)(i0 + row) * KK + c0 + kk];
        }
        __syncthreads();
#pragma unroll
        for (int kk = 0; kk < 32; kk++) {
            float4 w4 = *(const float4*)&W[(size_t)(c0 + kk) * FF + 4 * tx];
            unsigned long long w01 = pk2(w4.x, w4.y), w23 = pk2(w4.z, w4.w);
            float4 a4 = *(const float4*)&xs[kk][4 * ty];
            float av[4] = {a4.x, a4.y, a4.z, a4.w};
#pragma unroll
            for (int r = 0; r < 4; r++) {
                unsigned long long ar = pk2(av[r], av[r]);
                fma2(acc[r][0], ar, w01); fma2(acc[r][1], ar, w23);
            }
        }
        __syncthreads();
    }
#pragma unroll
    for (int r = 0; r < 4; r++) {
        float2 lo = upk(acc[r][0]), hi = upk(acc[r][1]);
        *(float4*)&g_h[(size_t)(i0 + 4 * ty + r) * FF + 4 * tx] = make_float4(lo.x, lo.y, hi.x, hi.y);
    }
}

// ============ B: hl/hr + fused scalars (atomic hrmax, |Wei|, |Wsi|) ============
__global__ void __launch_bounds__(256) k_hlr(const float* __restrict__ a,
                                             const float* __restrict__ Wsi,
                                             const float* __restrict__ Wei) {
    __shared__ float a1s[FF], a2s[FF], red[256];
    const int t = threadIdx.x;
    if (t < FF) a1s[t] = a[t]; else if (t < 2 * FF) a2s[t - FF] = a[t];
    __syncthreads();
    const int row = blockIdx.x * 256 + t;
    float s1 = 0.f, s2 = 0.f;
#pragma unroll
    for (int q = 0; q < 16; q++) {
        float4 h4 = *(const float4*)&g_h[(size_t)row * FF + 4 * q];
        s1 = fmaf(h4.x, a1s[4*q], fmaf(h4.y, a1s[4*q+1], fmaf(h4.z, a1s[4*q+2], fmaf(h4.w, a1s[4*q+3], s1))));
        s2 = fmaf(h4.x, a2s[4*q], fmaf(h4.y, a2s[4*q+1], fmaf(h4.z, a2s[4*q+2], fmaf(h4.w, a2s[4*q+3], s2))));
    }
    g_hl[row] = s1; g_hr[row] = s2;
    red[t] = s2;
    __syncthreads();
    for (int s = 128; s > 0; s >>= 1) { if (t < s) red[t] = fmaxf(red[t], red[t + s]); __syncthreads(); }
    if (t == 0) atomicMax(&g_hrmaxkey, fkey(red[0]));
    if (blockIdx.x == 0 && t == 0) { g_scalars[1] = fabsf(Wei[0]); g_scalars[2] = fabsf(Wsi[0]); }
}

// ============ Prep: per-64j-tile fp16 H^T image [tile][f][j/2] ============
__global__ void __launch_bounds__(256) k_prep_ht() {
    __shared__ float hs[64 * 68];
    const int t = threadIdx.x, T = blockIdx.x, j0 = T * 64;
#pragma unroll
    for (int k = 0; k < 4; k++) {
        int i4 = k * 256 + t;                 // float4 id 0..1023
        int j = i4 >> 4, f4 = i4 & 15;
        *(float4*)&hs[j * 68 + f4 * 4] = *(const float4*)&g_h[(size_t)(j0 + j) * FF + f4 * 4];
    }
    __syncthreads();
    const int f = t >> 2, jq = t & 3;         // thread: row f, 16 j's
    uint32_t pw[8];
#pragma unroll
    for (int s = 0; s < 8; s++) {
        int j = jq * 16 + 2 * s;
        pw[s] = f16x2_of(hs[j * 68 + f], hs[(j + 1) * 68 + f]);
    }
    uint32_t* dst = &g_hT[(uint32_t)T * 2048u + (uint32_t)f * 32u + (uint32_t)jq * 8u];
    *(uint4*)dst       = make_uint4(pw[0], pw[1], pw[2], pw[3]);
    *(uint4*)(dst + 4) = make_uint4(pw[4], pw[5], pw[6], pw[7]);
}

// ============ D: fused attention ============
__device__ __forceinline__ void issue_tile(const float* __restrict__ adj_ad,
                                           int i0, int j0, int Tt, int t,
                                           uint32_t ad_dst, uint32_t ht_dst) {
#pragma unroll
    for (int k = 0; k < 4; k++) {             // ad: 16KB
        int c = k * 256 + t, r = c >> 4, ch = c & 15;
        cpa16(ad_dst + r * 272 + ch * 16, adj_ad + (size_t)(i0 + r) * NN + j0 + ch * 4);
    }
#pragma unroll
    for (int k = 0; k < 2; k++) {             // Ht: 8KB (tile-blocked source)
        int c = k * 256 + t, f = c >> 3, ch = c & 7;
        cpa16(ht_dst + f * 144 + ch * 16, (const char*)&g_hT[(uint32_t)Tt * 2048u] + f * 128 + ch * 16);
    }
}

__global__ void __launch_bounds__(256, 2) k_attn(const float* __restrict__ adj_ad,
                                                 const int* __restrict__ adj) {
    extern __shared__ float4 smem4[];
    char* base = (char*)smem4;
    const uint32_t sb = smem_u32(base);

    const int t = threadIdx.x, wid = t >> 5, l = t & 31;
    const int i0 = blockIdx.x * BI, split = blockIdx.y, j0b = split * JCHUNK;
    const int T0 = split * NT;                // global 64j-tile base

    if (t < 128) *(float4*)(base + SM_HR + 16 * t) = *(const float4*)&g_hr[j0b + 4 * t];

    const float hrmax = fkeyinv(g_hrmaxkey);
    const float wei = g_scalars[1], wsi = g_scalars[2];
    const int r1 = t >> 2, q1 = t & 3;
    const float hl_r = g_hl[i0 + r1];
    float smax = hl_r + hrmax;
    const float m_r = fmaf(wei, fmaxf(smax, 0.2f * smax), wsi);

    const int iw = wid & 3, fh = wid >> 2;
    const uint32_t aRow = (uint32_t)((l & 7) | (l & 8));
    const uint32_t aOff = (uint32_t)(16 * iw + aRow) * 144u + (uint32_t)(((l >> 4) & 1) * 16);
    const uint32_t bRow = (uint32_t)(32 * fh + ((l & 7) | (((l >> 4) & 1) << 3)));
    const uint32_t bOff = bRow * 144u + (uint32_t)(((l >> 3) & 1) * 16);
    const uint32_t pA = sb + SM_P + aOff;

    float acc[16];
#pragma unroll
    for (int i = 0; i < 16; i++) acc[i] = 0.f;
    float zl = 0.f;

    // prologue: tiles 0,1 in flight; aj tile 0 in regs
    issue_tile(adj_ad, i0, j0b,      T0,     t, sb + SM_AD,         sb + SM_HT);          CP_COMMIT();
    issue_tile(adj_ad, i0, j0b + BJ, T0 + 1, t, sb + SM_AD + ADSTG, sb + SM_HT + 9216);   CP_COMMIT();
    int4 ajreg[4];
    {
        const int4* ap = (const int4*)&adj[(size_t)(i0 + r1) * NN + j0b + q1 * 16];
#pragma unroll
        for (int k = 0; k < 4; k++) ajreg[k] = ap[k];
    }

    for (int jt = 0; jt < NT; jt++) {
        const int jsrc = (jt + 2 < NT) ? jt + 2 : NT - 1;
        issue_tile(adj_ad, i0, j0b + jsrc * BJ, T0 + jsrc, t,
                   sb + SM_AD + ((jt + 2) % 3) * ADSTG, sb + SM_HT + ((jt + 2) & 3) * 9216);
        CP_COMMIT();
        CP_WAIT2();          // tile jt's ad + Ht landed
        __syncthreads();     // visibility + P free (all past phase2[jt-1])

        // ---- phase 1: p -> fp16 (aj from regs, ad from smem ring) ----
        {
            const float* ads = (const float*)(base + SM_AD + (jt % 3) * ADSTG) + r1 * 68 + q1 * 16;
            const float* hrs = (const float*)(base + SM_HR) + jt * 64 + q1 * 16;
            uint32_t pw[8];
#pragma unroll
            for (int k = 0; k < 4; k++) {
                float4 ad4 = *(const float4*)(ads + 4 * k);
                int4   aj4 = ajreg[k];
                float4 hr4 = *(const float4*)(hrs + 4 * k);
                float pv[4];
                {
                    float s = hl_r + hr4.x, lr = fmaxf(s, 0.2f * s);
                    pv[0] = (aj4.x > 0) ? __expf(fmaf(wei, lr, fmaf(wsi, ad4.x, -m_r))) : 0.f;
                }
                {
                    float s = hl_r + hr4.y, lr = fmaxf(s, 0.2f * s);
                    pv[1] = (aj4.y > 0) ? __expf(fmaf(wei, lr, fmaf(wsi, ad4.y, -m_r))) : 0.f;
                }
                {
                    float s = hl_r + hr4.z, lr = fmaxf(s, 0.2f * s);
                    pv[2] = (aj4.z > 0) ? __expf(fmaf(wei, lr, fmaf(wsi, ad4.z, -m_r))) : 0.f;
                }
                {
                    float s = hl_r + hr4.w, lr = fmaxf(s, 0.2f * s);
                    pv[3] = (aj4.w > 0) ? __expf(fmaf(wei, lr, fmaf(wsi, ad4.w, -m_r))) : 0.f;
                }
                zl += (pv[0] + pv[1]) + (pv[2] + pv[3]);
                pw[2*k]   = f16x2_of(pv[0], pv[1]);
                pw[2*k+1] = f16x2_of(pv[2], pv[3]);
            }
            char* pb = base + SM_P + r1 * 144 + q1 * 32;
            *(uint4*)pb        = make_uint4(pw[0], pw[1], pw[2], pw[3]);
            *(uint4*)(pb + 16) = make_uint4(pw[4], pw[5], pw[6], pw[7]);
        }

        // prefetch aj for tile jt+1 into regs (consumed next iteration)
        if (jt + 1 < NT) {
            const int4* ap = (const int4*)&adj[(size_t)(i0 + r1) * NN + j0b + (jt + 1) * BJ + q1 * 16];
#pragma unroll
            for (int k = 0; k < 4; k++) ajreg[k] = ap[k];
        }
        __syncthreads();     // P ready; ad stage free for reuse

        // ---- phase 2: 16 mma (single-variant fp16 H) ----
        const uint32_t hB = sb + SM_HT + (uint32_t)((jt & 3) * 9216) + bOff;
#pragma unroll
        for (int ks = 0; ks < 4; ks++) {
            const uint32_t ka = (uint32_t)ks * 32u;
            uint32_t ap4[4], bh0[4], bh1[4];
            ldm4(ap4, pA + ka);
            ldm4(bh0, hB + ka);
            ldm4(bh1, hB + 16u * 144u + ka);
            mma16816(acc + 0,  ap4, bh0[0], bh0[1]);
            mma16816(acc + 4,  ap4, bh0[2], bh0[3]);
            mma16816(acc + 8,  ap4, bh1[0], bh1[1]);
            mma16816(acc + 12, ap4, bh1[2], bh1[3]);
        }
    }
    CP_WAITALL();

    // z writeout
    zl += __shfl_xor_sync(0xffffffffu, zl, 1);
    zl += __shfl_xor_sync(0xffffffffu, zl, 2);
    if (q1 == 0) g_Z[split * NN + i0 + r1] = zl;

    // acc writeout
    {
        const int g = l >> 2, tig = l & 3;
#pragma unroll
        for (int nt = 0; nt < 4; nt++) {
            const int col = 32 * fh + 8 * nt + 2 * tig;
            const size_t b0 = ((size_t)split * NN + i0 + 16 * iw + g) * FF + col;
            const size_t b1 = b0 + (size_t)8 * FF;
            *(float2*)&g_acc[b0] = make_float2(acc[4 * nt + 0], acc[4 * nt + 1]);
            *(float2*)&g_acc[b1] = make_float2(acc[4 * nt + 2], acc[4 * nt + 3]);
        }
    }
}

// ============ E: combine, normalize, ELU ============
__global__ void __launch_bounds__(256) k_combine(float* __restrict__ out) {
    const int idx = blockIdx.x * 256 + threadIdx.x;
    const int i = idx >> 6;
    float num = 0.f, den = 0.f;
#pragma unroll
    for (int s = 0; s < SPLITJ; s++) {
        num += g_acc[(size_t)s * NN * FF + idx];
        den += g_Z[s * NN + i];
    }
    float r = num / den;
    out[idx] = (r > 0.0f) ? r : expm1f(r);
}

extern "C" void kernel_launch(void* const* d_in, const int* in_sizes, int n_in,
                              void* d_out, int out_size) {
    (void)in_sizes; (void)n_in; (void)out_size;
    const float* input  = (const float*)d_in[0];
    const float* W      = (const float*)d_in[1];
    const float* a      = (const float*)d_in[2];
    const float* W_si   = (const float*)d_in[3];
    const float* W_ei   = (const float*)d_in[4];
    const float* adj_ad = (const float*)d_in[5];
    const int*   adj    = (const int*)d_in[6];
    float* out = (float*)d_out;

    cudaFuncSetAttribute(k_attn, cudaFuncAttributeMaxDynamicSharedMemorySize, SM_BYTES);

    k_gemm_h<<<NN / 64, 256>>>(input, W);
    k_hlr<<<NN / 256, 256>>>(a, W_si, W_ei);
    k_prep_ht<<<NN / 64, 256>>>();
    k_attn<<<dim3(NN / BI, SPLITJ), 256, SM_BYTES>>>(adj_ad, adj);
    k_combine<<<NN * FF / 256, 256>>>(out);
}

// round 13
// speedup vs baseline: 1.5311x; 1.0484x over previous
#include <cuda_runtime.h>
#include <cuda_fp16.h>
#include <math.h>
#include <stdint.h>

#define NN 8192
#define KK 512
#define FF 64
#define SPLITJ 16
#define JCHUNK (NN / SPLITJ)   // 512
#define BI 64
#define BJ 64
#define NT (JCHUNK / BJ)       // 8

// smem layout (bytes)
#define HTSTG 9216
#define SM_HT 0                      // 6 stages = 55296
#define SM_P  (6 * HTSTG)            // 2 x 9216
#define SM_HR (SM_P + 2 * HTSTG)     // 2048
#define SM_BYTES (SM_HR + 2048)      // 75776

__device__ float g_hl[NN];
__device__ float g_hr[NN];
__device__ float g_scalars[4];                    // [1]=|W_ei| [2]=|W_si|
__device__ unsigned g_hrmaxkey;                   // order-preserving float key
__device__ uint32_t g_hT[128u * 2048u];           // [tile][f][jpair] f16x2, 1 MB
__device__ float g_acc[(size_t)SPLITJ * NN * FF]; // 32 MB
__device__ float g_Z[SPLITJ * NN];

// ---------- helpers ----------
__device__ __forceinline__ unsigned long long pk2(float x, float y) {
    unsigned long long r; asm("mov.b64 %0, {%1,%2};" : "=l"(r) : "f"(x), "f"(y)); return r;
}
__device__ __forceinline__ void fma2(unsigned long long& d, unsigned long long a, unsigned long long b) {
    asm("fma.rn.f32x2 %0, %1, %2, %0;" : "+l"(d) : "l"(a), "l"(b));
}
__device__ __forceinline__ float2 upk(unsigned long long v) {
    float2 f; asm("mov.b64 {%0,%1}, %2;" : "=f"(f.x), "=f"(f.y) : "l"(v)); return f;
}
__device__ __forceinline__ uint32_t smem_u32(const void* p) {
    uint32_t a; asm("{ .reg .u64 t; cvta.to.shared.u64 t, %1; cvt.u32.u64 %0, t; }" : "=r"(a) : "l"(p)); return a;
}
__device__ __forceinline__ void cpa16(uint32_t dst, const void* src) {
    asm volatile("cp.async.cg.shared.global [%0], [%1], 16;" :: "r"(dst), "l"(src));
}
#define CP_COMMIT()  asm volatile("cp.async.commit_group;" ::: "memory")
#define CP_WAIT4()   asm volatile("cp.async.wait_group 4;" ::: "memory")
#define CP_WAITALL() asm volatile("cp.async.wait_all;" ::: "memory")

__device__ __forceinline__ uint32_t f16x2_of(float lo, float hi) {
    uint32_t r; asm("cvt.rn.f16x2.f32 %0, %1, %2;" : "=r"(r) : "f"(hi), "f"(lo)); return r;
}
__device__ __forceinline__ void ldm4(uint32_t* r, uint32_t addr) {
    asm volatile("ldmatrix.sync.aligned.m8n8.x4.shared.b16 {%0,%1,%2,%3}, [%4];"
                 : "=r"(r[0]), "=r"(r[1]), "=r"(r[2]), "=r"(r[3]) : "r"(addr));
}
__device__ __forceinline__ void mma16816(float* d, const uint32_t* a, uint32_t b0, uint32_t b1) {
    asm("mma.sync.aligned.m16n8k16.row.col.f32.f16.f16.f32 "
        "{%0,%1,%2,%3}, {%4,%5,%6,%7}, {%8,%9}, {%0,%1,%2,%3};"
        : "+f"(d[0]), "+f"(d[1]), "+f"(d[2]), "+f"(d[3])
        : "r"(a[0]), "r"(a[1]), "r"(a[2]), "r"(a[3]), "r"(b0), "r"(b1));
}
__device__ __forceinline__ unsigned fkey(float f) {
    unsigned u = __float_as_uint(f);
    return (u & 0x80000000u) ? ~u : (u | 0x80000000u);
}
__device__ __forceinline__ float fkeyinv(unsigned k) {
    unsigned u = (k & 0x80000000u) ? (k ^ 0x80000000u) : ~k;
    return __uint_as_float(u);
}

// ============ A: gemm + fused hl/hr/hrmax/scalars + fp16 hT image ============
__global__ void __launch_bounds__(256) k_gemm_h(const float* __restrict__ X,
                                                const float* __restrict__ W,
                                                const float* __restrict__ a,
                                                const float* __restrict__ Wsi,
                                                const float* __restrict__ Wei) {
    __shared__ float xs[32][68];
    __shared__ float as1[FF], as2[FF], red[256];
    const int t = threadIdx.x, tx = t & 15, ty = t >> 4, i0 = blockIdx.x * 64;
    if (t < FF) as1[t] = a[t]; else if (t < 2 * FF) as2[t - FF] = a[t];

    unsigned long long acc[4][2];
#pragma unroll
    for (int r = 0; r < 4; r++) { acc[r][0] = 0ULL; acc[r][1] = 0ULL; }
    for (int c0 = 0; c0 < KK; c0 += 32) {
        __syncthreads();
#pragma unroll
        for (int q = 0; q < 8; q++) {
            int lin = t + 256 * q, row = lin >> 5, kk = lin & 31;
            xs[kk][row] = X[(size_t)(i0 + row) * KK + c0 + kk];
        }
        __syncthreads();
#pragma unroll
        for (int kk = 0; kk < 32; kk++) {
            float4 w4 = *(const float4*)&W[(size_t)(c0 + kk) * FF + 4 * tx];
            unsigned long long w01 = pk2(w4.x, w4.y), w23 = pk2(w4.z, w4.w);
            float4 a4 = *(const float4*)&xs[kk][4 * ty];
            float av[4] = {a4.x, a4.y, a4.z, a4.w};
#pragma unroll
            for (int r = 0; r < 4; r++) {
                unsigned long long ar = pk2(av[r], av[r]);
                fma2(acc[r][0], ar, w01); fma2(acc[r][1], ar, w23);
            }
        }
    }
    // unpack to av[r][c]
    float av[4][4];
#pragma unroll
    for (int r = 0; r < 4; r++) {
        float2 lo = upk(acc[r][0]), hi = upk(acc[r][1]);
        av[r][0] = lo.x; av[r][1] = lo.y; av[r][2] = hi.x; av[r][3] = hi.y;
    }
    // hT image: rows j=4ty+r, cols f=4tx+c
    const int T = blockIdx.x;
#pragma unroll
    for (int c = 0; c < 4; c++) {
        int f = 4 * tx + c;
        uint32_t u0 = f16x2_of(av[0][c], av[1][c]);
        uint32_t u1 = f16x2_of(av[2][c], av[3][c]);
        uint32_t bidx = (uint32_t)T * 2048u + (uint32_t)f * 32u + (uint32_t)(2 * ty);
        g_hT[bidx] = u0; g_hT[bidx + 1] = u1;
    }
    // hl/hr row dots (reduce across tx = 16 lanes within half-warp)
    float mloc = -3.4e38f;
#pragma unroll
    for (int r = 0; r < 4; r++) {
        float s1 = av[r][0] * as1[4*tx] + av[r][1] * as1[4*tx+1] + av[r][2] * as1[4*tx+2] + av[r][3] * as1[4*tx+3];
        float s2 = av[r][0] * as2[4*tx] + av[r][1] * as2[4*tx+1] + av[r][2] * as2[4*tx+2] + av[r][3] * as2[4*tx+3];
#pragma unroll
        for (int off = 8; off >= 1; off >>= 1) {
            s1 += __shfl_xor_sync(0xffffffffu, s1, off);
            s2 += __shfl_xor_sync(0xffffffffu, s2, off);
        }
        if (tx == 0) { g_hl[i0 + 4 * ty + r] = s1; g_hr[i0 + 4 * ty + r] = s2; }
        mloc = fmaxf(mloc, s2);
    }
    red[t] = mloc;
    __syncthreads();
    for (int s = 128; s > 0; s >>= 1) { if (t < s) red[t] = fmaxf(red[t], red[t + s]); __syncthreads(); }
    if (t == 0) atomicMax(&g_hrmaxkey, fkey(red[0]));
    if (blockIdx.x == 0 && t == 0) { g_scalars[1] = fabsf(Wei[0]); g_scalars[2] = fabsf(Wsi[0]); }
}

// ============ D: fused attention (reg phase-1, 6-stage Ht ring) ============
__global__ void __launch_bounds__(256, 2) k_attn(const float* __restrict__ adj_ad,
                                                 const int* __restrict__ adj) {
    extern __shared__ float4 smem4[];
    char* base = (char*)smem4;
    const uint32_t sb = smem_u32(base);

    const int t = threadIdx.x, wid = t >> 5, l = t & 31;
    const int i0 = blockIdx.x * BI, split = blockIdx.y, j0b = split * JCHUNK;
    const int T0 = split * NT;

    if (t < 128) *(float4*)(base + SM_HR + 16 * t) = *(const float4*)&g_hr[j0b + 4 * t];

    const float hrmax = fkeyinv(g_hrmaxkey);
    const float wei = g_scalars[1], wsi = g_scalars[2];
    const int r1 = t >> 2, q1 = t & 3;
    const float hl_r = g_hl[i0 + r1];
    float smax = hl_r + hrmax;
    const float m_r = fmaf(wei, fmaxf(smax, 0.2f * smax), wsi);

    const int iw = wid & 3, fh = wid >> 2;
    const uint32_t aRow = (uint32_t)((l & 7) | (l & 8));
    const uint32_t aOff = (uint32_t)(16 * iw + aRow) * 144u + (uint32_t)(((l >> 4) & 1) * 16);
    const uint32_t bRow = (uint32_t)(32 * fh + ((l & 7) | (((l >> 4) & 1) << 3)));
    const uint32_t bOff = bRow * 144u + (uint32_t)(((l >> 3) & 1) * 16);

    float acc[16];
#pragma unroll
    for (int i = 0; i < 16; i++) acc[i] = 0.f;
    float zl = 0.f;

    // prologue: Ht tiles 0..4 in flight; ad/aj tile 0 in regs
#pragma unroll
    for (int s = 0; s < 5; s++) {
        const char* src = (const char*)&g_hT[(uint32_t)(T0 + s) * 2048u];
#pragma unroll
        for (int k = 0; k < 2; k++) {
            int c = k * 256 + t, f = c >> 3, ch = c & 7;
            cpa16(sb + SM_HT + s * HTSTG + f * 144 + ch * 16, src + f * 128 + ch * 16);
        }
        CP_COMMIT();
    }
    float4 adreg[4];
    int4   ajreg[4];
    {
        const float4* ap = (const float4*)&adj_ad[(size_t)(i0 + r1) * NN + j0b + q1 * 16];
        const int4*   jp = (const int4*)&adj[(size_t)(i0 + r1) * NN + j0b + q1 * 16];
#pragma unroll
        for (int k = 0; k < 4; k++) { adreg[k] = ap[k]; ajreg[k] = jp[k]; }
    }
    __syncthreads();   // hr visible

    for (int jt = 0; jt < NT; jt++) {
        // ---- phase 1 (registers): p -> fp16 into P[jt&1] ----
        {
            const float* hrs = (const float*)(base + SM_HR) + jt * 64 + q1 * 16;
            uint32_t pw[8];
#pragma unroll
            for (int k = 0; k < 4; k++) {
                float4 ad4 = adreg[k];
                int4   aj4 = ajreg[k];
                float4 hr4 = *(const float4*)(hrs + 4 * k);
                float pv[4];
                {
                    float s = hl_r + hr4.x, lr = fmaxf(s, 0.2f * s);
                    pv[0] = (aj4.x > 0) ? __expf(fmaf(wei, lr, fmaf(wsi, ad4.x, -m_r))) : 0.f;
                }
                {
                    float s = hl_r + hr4.y, lr = fmaxf(s, 0.2f * s);
                    pv[1] = (aj4.y > 0) ? __expf(fmaf(wei, lr, fmaf(wsi, ad4.y, -m_r))) : 0.f;
                }
                {
                    float s = hl_r + hr4.z, lr = fmaxf(s, 0.2f * s);
                    pv[2] = (aj4.z > 0) ? __expf(fmaf(wei, lr, fmaf(wsi, ad4.z, -m_r))) : 0.f;
                }
                {
                    float s = hl_r + hr4.w, lr = fmaxf(s, 0.2f * s);
                    pv[3] = (aj4.w > 0) ? __expf(fmaf(wei, lr, fmaf(wsi, ad4.w, -m_r))) : 0.f;
                }
                zl += (pv[0] + pv[1]) + (pv[2] + pv[3]);
                pw[2*k]   = f16x2_of(pv[0], pv[1]);
                pw[2*k+1] = f16x2_of(pv[2], pv[3]);
            }
            char* pb = base + SM_P + (jt & 1) * HTSTG + r1 * 144 + q1 * 32;
            *(uint4*)pb        = make_uint4(pw[0], pw[1], pw[2], pw[3]);
            *(uint4*)(pb + 16) = make_uint4(pw[4], pw[5], pw[6], pw[7]);
        }

        // prefetch ad/aj for tile jt+1 into regs
        if (jt + 1 < NT) {
            const float4* ap = (const float4*)&adj_ad[(size_t)(i0 + r1) * NN + j0b + (jt + 1) * BJ + q1 * 16];
            const int4*   jp = (const int4*)&adj[(size_t)(i0 + r1) * NN + j0b + (jt + 1) * BJ + q1 * 16];
#pragma unroll
            for (int k = 0; k < 4; k++) { adreg[k] = ap[k]; ajreg[k] = jp[k]; }
        }

        CP_WAIT4();          // Ht tile jt landed
        __syncthreads();     // P[jt&1] complete; phase2[jt-1] done (stage + P reuse safe)

        // issue Ht(jt+5) into stage (jt+5)%6 (post-barrier: no reader race)
        {
            const int jsrc = (jt + 5 < NT) ? jt + 5 : NT - 1;
            const char* src = (const char*)&g_hT[(uint32_t)(T0 + jsrc) * 2048u];
            const int st = (jt + 5) % 6;
#pragma unroll
            for (int k = 0; k < 2; k++) {
                int c = k * 256 + t, f = c >> 3, ch = c & 7;
                cpa16(sb + SM_HT + st * HTSTG + f * 144 + ch * 16, src + f * 128 + ch * 16);
            }
            CP_COMMIT();
        }

        // ---- phase 2: 16 mma ----
        const uint32_t pA = sb + SM_P + (uint32_t)((jt & 1) * HTSTG) + aOff;
        const uint32_t hB = sb + SM_HT + (uint32_t)((jt % 6) * HTSTG) + bOff;
#pragma unroll
        for (int ks = 0; ks < 4; ks++) {
            const uint32_t ka = (uint32_t)ks * 32u;
            uint32_t ap4[4], bh0[4], bh1[4];
            ldm4(ap4, pA + ka);
            ldm4(bh0, hB + ka);
            ldm4(bh1, hB + 16u * 144u + ka);
            mma16816(acc + 0,  ap4, bh0[0], bh0[1]);
            mma16816(acc + 4,  ap4, bh0[2], bh0[3]);
            mma16816(acc + 8,  ap4, bh1[0], bh1[1]);
            mma16816(acc + 12, ap4, bh1[2], bh1[3]);
        }
    }
    CP_WAITALL();

    // z writeout
    zl += __shfl_xor_sync(0xffffffffu, zl, 1);
    zl += __shfl_xor_sync(0xffffffffu, zl, 2);
    if (q1 == 0) g_Z[split * NN + i0 + r1] = zl;

    // acc writeout
    {
        const int g = l >> 2, tig = l & 3;
#pragma unroll
        for (int nt = 0; nt < 4; nt++) {
            const int col = 32 * fh + 8 * nt + 2 * tig;
            const size_t b0 = ((size_t)split * NN + i0 + 16 * iw + g) * FF + col;
            const size_t b1 = b0 + (size_t)8 * FF;
            *(float2*)&g_acc[b0] = make_float2(acc[4 * nt + 0], acc[4 * nt + 1]);
            *(float2*)&g_acc[b1] = make_float2(acc[4 * nt + 2], acc[4 * nt + 3]);
        }
    }
}

// ============ E: combine, normalize, ELU ============
__global__ void __launch_bounds__(256) k_combine(float* __restrict__ out) {
    const int idx = blockIdx.x * 256 + threadIdx.x;
    const int i = idx >> 6;
    float num = 0.f, den = 0.f;
#pragma unroll
    for (int s = 0; s < SPLITJ; s++) {
        num += g_acc[(size_t)s * NN * FF + idx];
        den += g_Z[s * NN + i];
    }
    float r = num / den;
    out[idx] = (r > 0.0f) ? r : expm1f(r);
}

extern "C" void kernel_launch(void* const* d_in, const int* in_sizes, int n_in,
                              void* d_out, int out_size) {
    (void)in_sizes; (void)n_in; (void)out_size;
    const float* input  = (const float*)d_in[0];
    const float* W      = (const float*)d_in[1];
    const float* a      = (const float*)d_in[2];
    const float* W_si   = (const float*)d_in[3];
    const float* W_ei   = (const float*)d_in[4];
    const float* adj_ad = (const float*)d_in[5];
    const int*   adj    = (const int*)d_in[6];
    float* out = (float*)d_out;

    cudaFuncSetAttribute(k_attn, cudaFuncAttributeMaxDynamicSharedMemorySize, SM_BYTES);

    k_gemm_h<<<NN / 64, 256>>>(input, W, a, W_si, W_ei);
    k_attn<<<dim3(NN / BI, SPLITJ), 256, SM_BYTES>>>(adj_ad, adj);
    k_combine<<<NN * FF / 256, 256>>>(out);
}

// round 14
// speedup vs baseline: 1.7793x; 1.1621x over previous
#include <cuda_runtime.h>
#include <cuda_fp16.h>
#include <math.h>
#include <stdint.h>

#define NN 8192
#define KK 512
#define FF 64
#define SPLITJ 16
#define JCHUNK (NN / SPLITJ)   // 512
#define BI 64
#define BJ 64
#define NT (JCHUNK / BJ)       // 8

// k_attn smem layout (bytes)
#define HTSTG 9216
#define SM_HT 0                      // 6 stages = 55296
#define SM_P  (6 * HTSTG)            // 2 x 9216
#define SM_HR (SM_P + 2 * HTSTG)     // 2048
#define SM_BYTES (SM_HR + 2048)      // 75776

__device__ float g_hl[NN];
__device__ float g_hr[NN];
__device__ float g_scalars[4];                    // [1]=|W_ei| [2]=|W_si|
__device__ unsigned g_hrmaxkey;                   // order-preserving float key
__device__ uint32_t g_hT[128u * 2048u];           // [tile][f][jpair] f16x2, 1 MB
__device__ float g_acc[(size_t)SPLITJ * NN * FF]; // 32 MB
__device__ float g_Z[SPLITJ * NN];

// ---------- helpers ----------
__device__ __forceinline__ unsigned long long pk2(float x, float y) {
    unsigned long long r; asm("mov.b64 %0, {%1,%2};" : "=l"(r) : "f"(x), "f"(y)); return r;
}
__device__ __forceinline__ void fma2(unsigned long long& d, unsigned long long a, unsigned long long b) {
    asm("fma.rn.f32x2 %0, %1, %2, %0;" : "+l"(d) : "l"(a), "l"(b));
}
__device__ __forceinline__ float2 upk(unsigned long long v) {
    float2 f; asm("mov.b64 {%0,%1}, %2;" : "=f"(f.x), "=f"(f.y) : "l"(v)); return f;
}
__device__ __forceinline__ uint32_t smem_u32(const void* p) {
    uint32_t a; asm("{ .reg .u64 t; cvta.to.shared.u64 t, %1; cvt.u32.u64 %0, t; }" : "=r"(a) : "l"(p)); return a;
}
__device__ __forceinline__ void cpa16(uint32_t dst, const void* src) {
    asm volatile("cp.async.cg.shared.global [%0], [%1], 16;" :: "r"(dst), "l"(src));
}
#define CP_COMMIT()  asm volatile("cp.async.commit_group;" ::: "memory")
#define CP_WAIT1()   asm volatile("cp.async.wait_group 1;" ::: "memory")
#define CP_WAIT4()   asm volatile("cp.async.wait_group 4;" ::: "memory")
#define CP_WAITALL() asm volatile("cp.async.wait_all;" ::: "memory")

__device__ __forceinline__ uint32_t f16x2_of(float lo, float hi) {
    uint32_t r; asm("cvt.rn.f16x2.f32 %0, %1, %2;" : "=r"(r) : "f"(hi), "f"(lo)); return r;
}
__device__ __forceinline__ void ldm4(uint32_t* r, uint32_t addr) {
    asm volatile("ldmatrix.sync.aligned.m8n8.x4.shared.b16 {%0,%1,%2,%3}, [%4];"
                 : "=r"(r[0]), "=r"(r[1]), "=r"(r[2]), "=r"(r[3]) : "r"(addr));
}
__device__ __forceinline__ void mma16816(float* d, const uint32_t* a, uint32_t b0, uint32_t b1) {
    asm("mma.sync.aligned.m16n8k16.row.col.f32.f16.f16.f32 "
        "{%0,%1,%2,%3}, {%4,%5,%6,%7}, {%8,%9}, {%0,%1,%2,%3};"
        : "+f"(d[0]), "+f"(d[1]), "+f"(d[2]), "+f"(d[3])
        : "r"(a[0]), "r"(a[1]), "r"(a[2]), "r"(a[3]), "r"(b0), "r"(b1));
}
__device__ __forceinline__ unsigned fkey(float f) {
    unsigned u = __float_as_uint(f);
    return (u & 0x80000000u) ? ~u : (u | 0x80000000u);
}
__device__ __forceinline__ float fkeyinv(unsigned k) {
    unsigned u = (k & 0x80000000u) ? (k ^ 0x80000000u) : ~k;
    return __uint_as_float(u);
}

// ============ A: pipelined gemm + fused hl/hr/hrmax + fp16 hT image ============
// 32-row tiles, grid 256, 128 threads. W: 3-stage cp.async ring; X: reg-staged.
__global__ void __launch_bounds__(128) k_gemm_h(const float* __restrict__ X,
                                                const float* __restrict__ W,
                                                const float* __restrict__ a,
                                                const float* __restrict__ Wsi,
                                                const float* __restrict__ Wei) {
    __shared__ float xs[32][36];        // [kk][row], 144B stride
    __shared__ float ws[3][32][68];     // [stage][kk][col], 272B stride
    __shared__ float as1[FF], as2[FF], red[128];
    const int t = threadIdx.x, tx = t & 15, ty = t >> 4;   // ty 0..7
    const int i0 = blockIdx.x * 32;
    if (t < FF) as1[t] = a[t]; else as2[t - FF] = a[t];

    const uint32_t ws_sb = smem_u32(&ws[0][0][0]);

    // cp.async W chunk c0 into stage s (4 x 16B per thread)
    auto issueW = [&](int s, int c0) {
#pragma unroll
        for (int k = 0; k < 4; k++) {
            int c = k * 128 + t, row = c >> 4, col4 = (c & 15) * 4;
            cpa16(ws_sb + (uint32_t)((s * 2176 + row * 68 + col4) * 4),
                  W + (size_t)(c0 + row) * FF + col4);
        }
    };
    // X regs for chunk: thread row = t>>2, kk = (t&3)*8 .. +7
    const int xrow = t >> 2, xk0 = (t & 3) * 8;
    float4 xr0, xr1;
    auto loadX = [&](int c0) {
        const float* p = &X[(size_t)(i0 + xrow) * KK + c0 + xk0];
        xr0 = *(const float4*)p; xr1 = *(const float4*)(p + 4);
    };

    issueW(0, 0);  CP_COMMIT();
    issueW(1, 32); CP_COMMIT();
    loadX(0);

    unsigned long long acc[4][2];
#pragma unroll
    for (int r = 0; r < 4; r++) { acc[r][0] = 0ULL; acc[r][1] = 0ULL; }

    for (int ct = 0; ct < 16; ct++) {
        CP_WAIT1();            // W[ct] landed
        __syncthreads();       // xs + ws[(ct+2)%3] free (compute[ct-1] done)
        // STS X[ct] transposed
        xs[xk0 + 0][xrow] = xr0.x; xs[xk0 + 1][xrow] = xr0.y;
        xs[xk0 + 2][xrow] = xr0.z; xs[xk0 + 3][xrow] = xr0.w;
        xs[xk0 + 4][xrow] = xr1.x; xs[xk0 + 5][xrow] = xr1.y;
        xs[xk0 + 6][xrow] = xr1.z; xs[xk0 + 7][xrow] = xr1.w;
        if (ct + 1 < 16) loadX(32 * (ct + 1));
        { int cs = (ct + 2 < 16) ? ct + 2 : 15; issueW((ct + 2) % 3, 32 * cs); }
        CP_COMMIT();
        __syncthreads();       // xs ready
        const int st = ct % 3;
#pragma unroll
        for (int kk = 0; kk < 32; kk++) {
            float4 w4 = *(const float4*)&ws[st][kk][4 * tx];
            unsigned long long w01 = pk2(w4.x, w4.y), w23 = pk2(w4.z, w4.w);
            float4 a4 = *(const float4*)&xs[kk][4 * ty];
            float av[4] = {a4.x, a4.y, a4.z, a4.w};
#pragma unroll
            for (int r = 0; r < 4; r++) {
                unsigned long long ar = pk2(av[r], av[r]);
                fma2(acc[r][0], ar, w01); fma2(acc[r][1], ar, w23);
            }
        }
    }
    CP_WAITALL();

    float av[4][4];
#pragma unroll
    for (int r = 0; r < 4; r++) {
        float2 lo = upk(acc[r][0]), hi = upk(acc[r][1]);
        av[r][0] = lo.x; av[r][1] = lo.y; av[r][2] = hi.x; av[r][3] = hi.y;
    }
    // hT image: tile T = bx>>1, jpair base = (bx&1)*16 + 2ty
    {
        const int T = blockIdx.x >> 1;
        const uint32_t jp = (uint32_t)((blockIdx.x & 1) * 16 + 2 * ty);
#pragma unroll
        for (int c = 0; c < 4; c++) {
            int f = 4 * tx + c;
            uint32_t bidx = (uint32_t)T * 2048u + (uint32_t)f * 32u + jp;
            g_hT[bidx]     = f16x2_of(av[0][c], av[1][c]);
            g_hT[bidx + 1] = f16x2_of(av[2][c], av[3][c]);
        }
    }
    // hl/hr row dots, reduced across the 16 tx lanes
    float mloc = -3.4e38f;
#pragma unroll
    for (int r = 0; r < 4; r++) {
        float s1 = av[r][0]*as1[4*tx] + av[r][1]*as1[4*tx+1] + av[r][2]*as1[4*tx+2] + av[r][3]*as1[4*tx+3];
        float s2 = av[r][0]*as2[4*tx] + av[r][1]*as2[4*tx+1] + av[r][2]*as2[4*tx+2] + av[r][3]*as2[4*tx+3];
#pragma unroll
        for (int off = 8; off >= 1; off >>= 1) {
            s1 += __shfl_xor_sync(0xffffffffu, s1, off);
            s2 += __shfl_xor_sync(0xffffffffu, s2, off);
        }
        if (tx == 0) { g_hl[i0 + 4 * ty + r] = s1; g_hr[i0 + 4 * ty + r] = s2; }
        mloc = fmaxf(mloc, s2);
    }
    red[t] = mloc;
    __syncthreads();
    for (int s = 64; s > 0; s >>= 1) { if (t < s) red[t] = fmaxf(red[t], red[t + s]); __syncthreads(); }
    if (t == 0) atomicMax(&g_hrmaxkey, fkey(red[0]));
    if (blockIdx.x == 0 && t == 0) { g_scalars[1] = fabsf(Wei[0]); g_scalars[2] = fabsf(Wsi[0]); }
}

// ============ D: fused attention (reg phase-1, 6-stage Ht ring) — unchanged ============
__global__ void __launch_bounds__(256, 2) k_attn(const float* __restrict__ adj_ad,
                                                 const int* __restrict__ adj) {
    extern __shared__ float4 smem4[];
    char* base = (char*)smem4;
    const uint32_t sb = smem_u32(base);

    const int t = threadIdx.x, wid = t >> 5, l = t & 31;
    const int i0 = blockIdx.x * BI, split = blockIdx.y, j0b = split * JCHUNK;
    const int T0 = split * NT;

    if (t < 128) *(float4*)(base + SM_HR + 16 * t) = *(const float4*)&g_hr[j0b + 4 * t];

    const float hrmax = fkeyinv(g_hrmaxkey);
    const float wei = g_scalars[1], wsi = g_scalars[2];
    const int r1 = t >> 2, q1 = t & 3;
    const float hl_r = g_hl[i0 + r1];
    float smax = hl_r + hrmax;
    const float m_r = fmaf(wei, fmaxf(smax, 0.2f * smax), wsi);

    const int iw = wid & 3, fh = wid >> 2;
    const uint32_t aRow = (uint32_t)((l & 7) | (l & 8));
    const uint32_t aOff = (uint32_t)(16 * iw + aRow) * 144u + (uint32_t)(((l >> 4) & 1) * 16);
    const uint32_t bRow = (uint32_t)(32 * fh + ((l & 7) | (((l >> 4) & 1) << 3)));
    const uint32_t bOff = bRow * 144u + (uint32_t)(((l >> 3) & 1) * 16);

    float acc[16];
#pragma unroll
    for (int i = 0; i < 16; i++) acc[i] = 0.f;
    float zl = 0.f;

#pragma unroll
    for (int s = 0; s < 5; s++) {
        const char* src = (const char*)&g_hT[(uint32_t)(T0 + s) * 2048u];
#pragma unroll
        for (int k = 0; k < 2; k++) {
            int c = k * 256 + t, f = c >> 3, ch = c & 7;
            cpa16(sb + SM_HT + s * HTSTG + f * 144 + ch * 16, src + f * 128 + ch * 16);
        }
        CP_COMMIT();
    }
    float4 adreg[4];
    int4   ajreg[4];
    {
        const float4* ap = (const float4*)&adj_ad[(size_t)(i0 + r1) * NN + j0b + q1 * 16];
        const int4*   jp = (const int4*)&adj[(size_t)(i0 + r1) * NN + j0b + q1 * 16];
#pragma unroll
        for (int k = 0; k < 4; k++) { adreg[k] = ap[k]; ajreg[k] = jp[k]; }
    }
    __syncthreads();

    for (int jt = 0; jt < NT; jt++) {
        {
            const float* hrs = (const float*)(base + SM_HR) + jt * 64 + q1 * 16;
            uint32_t pw[8];
#pragma unroll
            for (int k = 0; k < 4; k++) {
                float4 ad4 = adreg[k];
                int4   aj4 = ajreg[k];
                float4 hr4 = *(const float4*)(hrs + 4 * k);
                float pv[4];
                {
                    float s = hl_r + hr4.x, lr = fmaxf(s, 0.2f * s);
                    pv[0] = (aj4.x > 0) ? __expf(fmaf(wei, lr, fmaf(wsi, ad4.x, -m_r))) : 0.f;
                }
                {
                    float s = hl_r + hr4.y, lr = fmaxf(s, 0.2f * s);
                    pv[1] = (aj4.y > 0) ? __expf(fmaf(wei, lr, fmaf(wsi, ad4.y, -m_r))) : 0.f;
                }
                {
                    float s = hl_r + hr4.z, lr = fmaxf(s, 0.2f * s);
                    pv[2] = (aj4.z > 0) ? __expf(fmaf(wei, lr, fmaf(wsi, ad4.z, -m_r))) : 0.f;
                }
                {
                    float s = hl_r + hr4.w, lr = fmaxf(s, 0.2f * s);
                    pv[3] = (aj4.w > 0) ? __expf(fmaf(wei, lr, fmaf(wsi, ad4.w, -m_r))) : 0.f;
                }
                zl += (pv[0] + pv[1]) + (pv[2] + pv[3]);
                pw[2*k]   = f16x2_of(pv[0], pv[1]);
                pw[2*k+1] = f16x2_of(pv[2], pv[3]);
            }
            char* pb = base + SM_P + (jt & 1) * HTSTG + r1 * 144 + q1 * 32;
            *(uint4*)pb        = make_uint4(pw[0], pw[1], pw[2], pw[3]);
            *(uint4*)(pb + 16) = make_uint4(pw[4], pw[5], pw[6], pw[7]);
        }

        if (jt + 1 < NT) {
            const float4* ap = (const float4*)&adj_ad[(size_t)(i0 + r1) * NN + j0b + (jt + 1) * BJ + q1 * 16];
            const int4*   jp = (const int4*)&adj[(size_t)(i0 + r1) * NN + j0b + (jt + 1) * BJ + q1 * 16];
#pragma unroll
            for (int k = 0; k < 4; k++) { adreg[k] = ap[k]; ajreg[k] = jp[k]; }
        }

        CP_WAIT4();
        __syncthreads();

        {
            const int jsrc = (jt + 5 < NT) ? jt + 5 : NT - 1;
            const char* src = (const char*)&g_hT[(uint32_t)(T0 + jsrc) * 2048u];
            const int st = (jt + 5) % 6;
#pragma unroll
            for (int k = 0; k < 2; k++) {
                int c = k * 256 + t, f = c >> 3, ch = c & 7;
                cpa16(sb + SM_HT + st * HTSTG + f * 144 + ch * 16, src + f * 128 + ch * 16);
            }
            CP_COMMIT();
        }

        const uint32_t pA = sb + SM_P + (uint32_t)((jt & 1) * HTSTG) + aOff;
        const uint32_t hB = sb + SM_HT + (uint32_t)((jt % 6) * HTSTG) + bOff;
#pragma unroll
        for (int ks = 0; ks < 4; ks++) {
            const uint32_t ka = (uint32_t)ks * 32u;
            uint32_t ap4[4], bh0[4], bh1[4];
            ldm4(ap4, pA + ka);
            ldm4(bh0, hB + ka);
            ldm4(bh1, hB + 16u * 144u + ka);
            mma16816(acc + 0,  ap4, bh0[0], bh0[1]);
            mma16816(acc + 4,  ap4, bh0[2], bh0[3]);
            mma16816(acc + 8,  ap4, bh1[0], bh1[1]);
            mma16816(acc + 12, ap4, bh1[2], bh1[3]);
        }
    }
    CP_WAITALL();

    zl += __shfl_xor_sync(0xffffffffu, zl, 1);
    zl += __shfl_xor_sync(0xffffffffu, zl, 2);
    if (q1 == 0) g_Z[split * NN + i0 + r1] = zl;

    {
        const int g = l >> 2, tig = l & 3;
#pragma unroll
        for (int nt = 0; nt < 4; nt++) {
            const int col = 32 * fh + 8 * nt + 2 * tig;
            const size_t b0 = ((size_t)split * NN + i0 + 16 * iw + g) * FF + col;
            const size_t b1 = b0 + (size_t)8 * FF;
            *(float2*)&g_acc[b0] = make_float2(acc[4 * nt + 0], acc[4 * nt + 1]);
            *(float2*)&g_acc[b1] = make_float2(acc[4 * nt + 2], acc[4 * nt + 3]);
        }
    }
}

// ============ E: combine (float4), normalize, ELU ============
__global__ void __launch_bounds__(256) k_combine(float* __restrict__ out) {
    const int v = blockIdx.x * 256 + threadIdx.x;   // float4 id
    const int i = v >> 4;                            // row
    float4 num = make_float4(0.f, 0.f, 0.f, 0.f);
    float den = 0.f;
#pragma unroll
    for (int s = 0; s < SPLITJ; s++) {
        float4 x = *(const float4*)&g_acc[(size_t)s * NN * FF + (size_t)v * 4];
        num.x += x.x; num.y += x.y; num.z += x.z; num.w += x.w;
        den += g_Z[s * NN + i];
    }
    float inv = 1.0f / den;
    float4 r = make_float4(num.x * inv, num.y * inv, num.z * inv, num.w * inv);
    r.x = (r.x > 0.f) ? r.x : expm1f(r.x);
    r.y = (r.y > 0.f) ? r.y : expm1f(r.y);
    r.z = (r.z > 0.f) ? r.z : expm1f(r.z);
    r.w = (r.w > 0.f) ? r.w : expm1f(r.w);
    *(float4*)&out[(size_t)v * 4] = r;
}

extern "C" void kernel_launch(void* const* d_in, const int* in_sizes, int n_in,
                              void* d_out, int out_size) {
    (void)in_sizes; (void)n_in; (void)out_size;
    const float* input  = (const float*)d_in[0];
    const float* W      = (const float*)d_in[1];
    const float* a      = (const float*)d_in[2];
    const float* W_si   = (const float*)d_in[3];
    const float* W_ei   = (const float*)d_in[4];
    const float* adj_ad = (const float*)d_in[5];
    const int*   adj    = (const int*)d_in[6];
    float* out = (float*)d_out;

    cudaFuncSetAttribute(k_attn, cudaFuncAttributeMaxDynamicSharedMemorySize, SM_BYTES);

    k_gemm_h<<<NN / 32, 128>>>(input, W, a, W_si, W_ei);
    k_attn<<<dim3(NN / BI, SPLITJ), 256, SM_BYTES>>>(adj_ad, adj);
    k_combine<<<NN * FF / 1024, 256>>>(out);
}